// round 1
// baseline (speedup 1.0000x reference)
#include <cuda_runtime.h>
#include <cstdint>
#include <math.h>

// Problem dims
#define HW   32768
#define CCH  256
#define HH   128
#define WWD  256
#define NPIX 65536      // B * HW
#define PPTS 9
#define GRP  8

// ---------------- scratch (static device globals; no allocation) ------------
__device__ float g_mean[2 * NPIX];
__device__ float g_rstd[2 * NPIX];
__device__ float g_value[(size_t)NPIX * CCH];    // (b*HW+n, c)  64 MiB
__device__ float g_logits[(size_t)NPIX * 128];   // padded 81 -> 128, 32 MiB
__device__ float g_wts[(size_t)NPIX * 72];       // softmaxed, (n, p*8+g)
__device__ float g_agg[(size_t)NPIX * CCH];      // 64 MiB
__device__ float g_Wpad[CCH * 128];              // [Ww | Wk | 0] padded to 128 cols
__device__ float g_bpad[128];

// ---------------- K1: per-pixel LN stats for feats1 & feats2 ----------------
__global__ __launch_bounds__(128) void stats_kernel(const float* __restrict__ f1,
                                                    const float* __restrict__ f2) {
    const int pg = blockIdx.x * 128 + threadIdx.x;  // global pixel (b*HW+n)
    const int which = blockIdx.y;                   // 0 -> feats1, 1 -> feats2
    const float* f = which ? f2 : f1;
    const int b = pg >> 15;
    const int n = pg & (HW - 1);
    const float* base = f + ((size_t)b << 23) + n;  // b*C*HW
    float s = 0.f, s2 = 0.f;
#pragma unroll 8
    for (int c = 0; c < CCH; ++c) {
        float v = base[(size_t)c << 15];
        s += v; s2 += v * v;
    }
    const float m = s * (1.f / 256.f);
    const float var = s2 * (1.f / 256.f) - m * m;
    g_mean[which * NPIX + pg] = m;
    g_rstd[which * NPIX + pg] = rsqrtf(var + 1e-5f);
}

// ---------------- K2: build padded [Ww|Wk] weight + bias --------------------
__global__ void concat_kernel(const float* __restrict__ Ww, const float* __restrict__ bw,
                              const float* __restrict__ Wk, const float* __restrict__ bk) {
    int idx = blockIdx.x * 256 + threadIdx.x;       // 128*256 = 32768
    if (idx < CCH * 128) {
        int c = idx >> 7, j = idx & 127;
        float v = 0.f;
        if (j < 72)      v = Ww[c * 72 + j];
        else if (j < 81) v = Wk[c * 9 + (j - 72)];
        g_Wpad[idx] = v;
    }
    if (idx < 128)
        g_bpad[idx] = (idx < 72) ? bw[idx] : ((idx < 81) ? bk[idx - 72] : 0.f);
}

// ---------------- K3: fused LN + SGEMM  (A = LN(feats)[m,c], C = A@W + b) ----
// MODE 0: feats2/norm2 -> g_value (NCOLS=256).  MODE 1: feats1/norm1 -> g_logits (NCOLS=128)
template <int NCOLS, int MODE>
__global__ __launch_bounds__(256) void gemm_ln(const float* __restrict__ feats,
                                               const float* __restrict__ gamma,
                                               const float* __restrict__ beta,
                                               const float* __restrict__ W,
                                               const float* __restrict__ bias) {
    __shared__ float As[8][128];
    __shared__ float Bs[8][128];
    __shared__ float smM[128], smR[128];

    const int t  = threadIdx.x;
    const int m0 = blockIdx.y * 128;
    const int j0 = blockIdx.x * 128;
    const int b  = m0 >> 15;
    const int n0 = m0 & (HW - 1);
    const int which = (MODE == 0) ? 1 : 0;   // stats index: value path uses feats2

    if (t < 128) {
        smM[t] = g_mean[which * NPIX + m0 + t];
        smR[t] = g_rstd[which * NPIX + m0 + t];
    }
    __syncthreads();

    const int ak = t >> 5;            // 0..7 (k within tile)
    const int am = (t & 31) << 2;     // 0..124 (m / j within tile, float4)
    const int tx = t & 15;            // j fragment
    const int ty = t >> 4;            // m fragment

    float pm[4], pr[4];
#pragma unroll
    for (int i = 0; i < 4; ++i) { pm[i] = smM[am + i]; pr[i] = smR[am + i]; }

    const float* Wp = (MODE == 1) ? g_Wpad : W;
    const float* bp = (MODE == 1) ? g_bpad : bias;

    float acc[8][8];
#pragma unroll
    for (int i = 0; i < 8; ++i)
#pragma unroll
        for (int j = 0; j < 8; ++j) acc[i][j] = 0.f;

    for (int k0 = 0; k0 < CCH; k0 += 8) {
        const int c = k0 + ak;
        float4 x4 = *reinterpret_cast<const float4*>(
            feats + (((size_t)b * CCH + c) << 15) + n0 + am);
        const float ga = __ldg(gamma + c), be = __ldg(beta + c);
        float4 a4;
        a4.x = (x4.x - pm[0]) * pr[0] * ga + be;
        a4.y = (x4.y - pm[1]) * pr[1] * ga + be;
        a4.z = (x4.z - pm[2]) * pr[2] * ga + be;
        a4.w = (x4.w - pm[3]) * pr[3] * ga + be;
        *reinterpret_cast<float4*>(&As[ak][am]) = a4;

        float4 b4 = *reinterpret_cast<const float4*>(Wp + (size_t)c * NCOLS + j0 + am);
        *reinterpret_cast<float4*>(&Bs[ak][am]) = b4;

        __syncthreads();
#pragma unroll
        for (int kk = 0; kk < 8; ++kk) {
            float a[8], w[8];
            *reinterpret_cast<float4*>(a)     = *reinterpret_cast<const float4*>(&As[kk][ty * 8]);
            *reinterpret_cast<float4*>(a + 4) = *reinterpret_cast<const float4*>(&As[kk][ty * 8 + 4]);
            *reinterpret_cast<float4*>(w)     = *reinterpret_cast<const float4*>(&Bs[kk][tx * 8]);
            *reinterpret_cast<float4*>(w + 4) = *reinterpret_cast<const float4*>(&Bs[kk][tx * 8 + 4]);
#pragma unroll
            for (int i = 0; i < 8; ++i)
#pragma unroll
                for (int j = 0; j < 8; ++j)
                    acc[i][j] = fmaf(a[i], w[j], acc[i][j]);
        }
        __syncthreads();
    }

    float* Co = (MODE == 0) ? g_value : g_logits;
    float bb[8];
#pragma unroll
    for (int j = 0; j < 8; ++j) bb[j] = bp[j0 + tx * 8 + j];
#pragma unroll
    for (int i = 0; i < 8; ++i) {
        const size_t row = (size_t)(m0 + ty * 8 + i);
        float4 r0, r1;
        r0.x = acc[i][0] + bb[0]; r0.y = acc[i][1] + bb[1];
        r0.z = acc[i][2] + bb[2]; r0.w = acc[i][3] + bb[3];
        r1.x = acc[i][4] + bb[4]; r1.y = acc[i][5] + bb[5];
        r1.z = acc[i][6] + bb[6]; r1.w = acc[i][7] + bb[7];
        *reinterpret_cast<float4*>(Co + row * NCOLS + j0 + tx * 8)     = r0;
        *reinterpret_cast<float4*>(Co + row * NCOLS + j0 + tx * 8 + 4) = r1;
    }
}

// ---------------- K4: softmax over points + keypoint emit -------------------
__global__ __launch_bounds__(256) void softmax_kp_kernel(const float* __restrict__ anchor,
                                                         float* __restrict__ kp_out) {
    const int pid = blockIdx.x * 256 + threadIdx.x;  // < NPIX
    const float* row = g_logits + (size_t)pid * 128;
    float l[72], off[PPTS];
#pragma unroll
    for (int j = 0; j < 72; ++j) l[j] = row[j];
#pragma unroll
    for (int p = 0; p < PPTS; ++p) off[p] = row[72 + p];

#pragma unroll
    for (int g = 0; g < GRP; ++g) {
        float mx = l[g];
#pragma unroll
        for (int p = 1; p < PPTS; ++p) mx = fmaxf(mx, l[p * 8 + g]);
        float s = 0.f;
#pragma unroll
        for (int p = 0; p < PPTS; ++p) {
            float e = __expf(l[p * 8 + g] - mx);
            l[p * 8 + g] = e; s += e;
        }
        const float inv = 1.f / s;
#pragma unroll
        for (int p = 0; p < PPTS; ++p)
            g_wts[(size_t)pid * 72 + p * 8 + g] = l[p * 8 + g] * inv;
    }
    const float ax = anchor[2 * pid], ay = anchor[2 * pid + 1];
#pragma unroll
    for (int p = 0; p < PPTS; ++p) {
        kp_out[((size_t)pid * PPTS + p) * 2]     = ax + off[p];
        kp_out[((size_t)pid * PPTS + p) * 2 + 1] = ay;
    }
}

// ---------------- K5: deformable bilinear gather + group-weighted sum -------
__global__ __launch_bounds__(256) void agg_kernel(const float* __restrict__ kp) {
    const int pg = blockIdx.x;
    const int t  = threadIdx.x;       // channel c
    __shared__ float w_s[72];
    __shared__ int   sx0[PPTS], sy0[PPTS];
    __shared__ float swx[PPTS], swy[PPTS];

    if (t < 72) w_s[t] = g_wts[(size_t)pg * 72 + t];
    if (t < PPTS) {
        const float kx = kp[((size_t)pg * PPTS + t) * 2];
        const float ky = kp[((size_t)pg * PPTS + t) * 2 + 1];
        const float x = kx * (float)WWD - 0.5f;
        const float y = ky * (float)HH  - 0.5f;
        const float xf = floorf(x), yf = floorf(y);
        sx0[t] = (int)xf; sy0[t] = (int)yf;
        swx[t] = x - xf;  swy[t] = y - yf;
    }
    __syncthreads();

    const int b = pg >> 15;
    const float* vb = g_value + ((size_t)b << 23);  // b*HW*C
    const int g = t >> 5;
    float acc = 0.f;
#pragma unroll
    for (int p = 0; p < PPTS; ++p) {
        const int x0 = sx0[p], y0 = sy0[p];
        const float wx = swx[p], wy = swy[p];
        float v00 = 0.f, v01 = 0.f, v10 = 0.f, v11 = 0.f;
        const bool yv0 = (y0 >= 0) & (y0 < HH);
        const bool yv1 = (y0 + 1 >= 0) & (y0 + 1 < HH);
        const bool xv0 = (x0 >= 0) & (x0 < WWD);
        const bool xv1 = (x0 + 1 >= 0) & (x0 + 1 < WWD);
        if (yv0 && xv0) v00 = vb[((size_t)(y0 * WWD + x0)       << 8) + t];
        if (yv0 && xv1) v01 = vb[((size_t)(y0 * WWD + x0 + 1)   << 8) + t];
        if (yv1 && xv0) v10 = vb[((size_t)((y0 + 1) * WWD + x0) << 8) + t];
        if (yv1 && xv1) v11 = vb[((size_t)((y0 + 1) * WWD + x0 + 1) << 8) + t];
        const float s = v00 * (1.f - wx) * (1.f - wy) + v01 * wx * (1.f - wy)
                      + v10 * (1.f - wx) * wy         + v11 * wx * wy;
        acc = fmaf(w_s[p * 8 + g], s, acc);
    }
    g_agg[((size_t)pg << 8) + t] = acc;
}

// ---------------- K6: SGEMM with transposed output (agg @ Wo -> out[b,c,n]) -
__global__ __launch_bounds__(256) void gemm_t(const float* __restrict__ Wo,
                                              const float* __restrict__ bo,
                                              float* __restrict__ out) {
    __shared__ float As[8][132];   // padded to kill store conflicts
    __shared__ float Bs[8][128];

    const int t  = threadIdx.x;
    const int m0 = blockIdx.y * 128;
    const int j0 = blockIdx.x * 128;
    const int b  = m0 >> 15;
    const int n0 = m0 & (HW - 1);

    const int am  = t >> 1;            // 0..127
    const int ak4 = (t & 1) << 2;      // 0 or 4
    const int bk  = t >> 5;
    const int bj  = (t & 31) << 2;
    const int tx  = t & 15;            // m fragment
    const int ty  = t >> 4;            // j fragment

    float acc[8][8];                   // acc[j][m]
#pragma unroll
    for (int i = 0; i < 8; ++i)
#pragma unroll
        for (int j = 0; j < 8; ++j) acc[i][j] = 0.f;

    for (int k0 = 0; k0 < CCH; k0 += 8) {
        float4 a4 = *reinterpret_cast<const float4*>(
            g_agg + (((size_t)(m0 + am)) << 8) + k0 + ak4);
        As[ak4 + 0][am] = a4.x; As[ak4 + 1][am] = a4.y;
        As[ak4 + 2][am] = a4.z; As[ak4 + 3][am] = a4.w;

        float4 b4 = *reinterpret_cast<const float4*>(Wo + (size_t)(k0 + bk) * CCH + j0 + bj);
        *reinterpret_cast<float4*>(&Bs[bk][bj]) = b4;

        __syncthreads();
#pragma unroll
        for (int kk = 0; kk < 8; ++kk) {
            float a[8], w[8];
            *reinterpret_cast<float4*>(a)     = *reinterpret_cast<const float4*>(&As[kk][tx * 8]);
            *reinterpret_cast<float4*>(a + 4) = *reinterpret_cast<const float4*>(&As[kk][tx * 8 + 4]);
            *reinterpret_cast<float4*>(w)     = *reinterpret_cast<const float4*>(&Bs[kk][ty * 8]);
            *reinterpret_cast<float4*>(w + 4) = *reinterpret_cast<const float4*>(&Bs[kk][ty * 8 + 4]);
#pragma unroll
            for (int jj = 0; jj < 8; ++jj)
#pragma unroll
                for (int ii = 0; ii < 8; ++ii)
                    acc[jj][ii] = fmaf(w[jj], a[ii], acc[jj][ii]);
        }
        __syncthreads();
    }

#pragma unroll
    for (int jj = 0; jj < 8; ++jj) {
        const int j = j0 + ty * 8 + jj;
        const float bv = __ldg(bo + j);
        float4 r0, r1;
        r0.x = acc[jj][0] + bv; r0.y = acc[jj][1] + bv;
        r0.z = acc[jj][2] + bv; r0.w = acc[jj][3] + bv;
        r1.x = acc[jj][4] + bv; r1.y = acc[jj][5] + bv;
        r1.z = acc[jj][6] + bv; r1.w = acc[jj][7] + bv;
        float* dst = out + (((size_t)b * CCH + j) << 15) + n0 + tx * 8;
        *reinterpret_cast<float4*>(dst)     = r0;
        *reinterpret_cast<float4*>(dst + 4) = r1;
    }
}

// ---------------- launch -----------------------------------------------------
extern "C" void kernel_launch(void* const* d_in, const int* in_sizes, int n_in,
                              void* d_out, int out_size) {
    const float* feats1 = (const float*)d_in[0];
    const float* feats2 = (const float*)d_in[1];
    const float* anchor = (const float*)d_in[2];
    const float* n1g = (const float*)d_in[3];
    const float* n1b = (const float*)d_in[4];
    const float* n2g = (const float*)d_in[5];
    const float* n2b = (const float*)d_in[6];
    const float* Wv  = (const float*)d_in[7];
    const float* bv  = (const float*)d_in[8];
    const float* Ww  = (const float*)d_in[9];
    const float* bw  = (const float*)d_in[10];
    const float* Wk  = (const float*)d_in[11];
    const float* bk  = (const float*)d_in[12];
    const float* Wo  = (const float*)d_in[13];
    const float* bo  = (const float*)d_in[14];

    float* out    = (float*)d_out;
    float* kp_out = out + (size_t)16777216;   // B*C*H*W

    stats_kernel<<<dim3(NPIX / 128, 2), 128>>>(feats1, feats2);
    concat_kernel<<<128, 256>>>(Ww, bw, Wk, bk);
    gemm_ln<256, 0><<<dim3(2, NPIX / 128), 256>>>(feats2, n2g, n2b, Wv, bv);
    gemm_ln<128, 1><<<dim3(1, NPIX / 128), 256>>>(feats1, n1g, n1b, Ww, bw);
    softmax_kp_kernel<<<NPIX / 256, 256>>>(anchor, kp_out);
    agg_kernel<<<NPIX, 256>>>(kp_out);
    gemm_t<<<dim3(2, NPIX / 128), 256>>>(Wo, bo, out);
}

// round 4
// speedup vs baseline: 1.8350x; 1.8350x over previous
#include <cuda_runtime.h>
#include <cstdint>
#include <math.h>

// Problem dims
#define HW   32768
#define CCH  256
#define HH   128
#define WWD  256
#define NPIX 65536      // B * HW
#define PPTS 9
#define GRP  8

#define PADM 136        // SMEM row stride (floats); 136 % 32 == 8 -> conflict-free frags

// ---------------- scratch (static device globals; no allocation) ------------
__device__ float g_mean[2 * NPIX];
__device__ float g_rstd[2 * NPIX];
__device__ float g_value[(size_t)NPIX * CCH];     // (pixel, j)
__device__ float g_logits[(size_t)NPIX * 128];    // padded; only cols 0..71 consumed
__device__ float g_wts[(size_t)NPIX * 72];
__device__ float g_agg[(size_t)NPIX * CCH];
__device__ float g_Wpad[CCH * 128];               // [k][j] = [Ww | Wk | 0]
__device__ float g_bpad[128];

__device__ __forceinline__ uint32_t f2tf32(float f) {
    uint32_t r;
    asm("cvt.rna.tf32.f32 %0, %1;" : "=r"(r) : "f"(f));
    return r;
}

// ---------------- K1: per-pixel LN stats ------------------------------------
__global__ __launch_bounds__(128) void stats_kernel(const float* __restrict__ f1,
                                                    const float* __restrict__ f2) {
    const int pg = blockIdx.x * 128 + threadIdx.x;
    const int which = blockIdx.y;
    const float* f = which ? f2 : f1;
    const int b = pg >> 15;
    const int n = pg & (HW - 1);
    const float* base = f + ((size_t)b << 23) + n;
    float s = 0.f, s2 = 0.f;
#pragma unroll 8
    for (int c = 0; c < CCH; ++c) {
        float v = base[(size_t)c << 15];
        s += v; s2 += v * v;
    }
    const float m = s * (1.f / 256.f);
    const float var = s2 * (1.f / 256.f) - m * m;
    g_mean[which * NPIX + pg] = m;
    g_rstd[which * NPIX + pg] = rsqrtf(var + 1e-5f);
}

// ---------------- K2: build padded [Ww|Wk] weight + bias --------------------
__global__ void prep_kernel(const float* __restrict__ Ww, const float* __restrict__ bw,
                            const float* __restrict__ Wk, const float* __restrict__ bk) {
    int idx = blockIdx.x * 256 + threadIdx.x;       // 128*256 = 32768
    if (idx < CCH * 128) {
        int c = idx >> 7, j = idx & 127;
        float v = 0.f;
        if (j < 72)      v = Ww[c * 72 + j];
        else if (j < 81) v = Wk[c * 9 + (j - 72)];
        g_Wpad[idx] = v;
    }
    if (idx < 128)
        g_bpad[idx] = (idx < 72) ? bw[idx] : ((idx < 81) ? bk[idx - 72] : 0.f);
}

// ---------------- K3: tf32 mma.sync GEMM (3 modes) ---------------------------
// MODE 0: C[pixel,j] = LN(feats2) @ Wv + bv      -> g_value   grid (512, 2)
// MODE 1: C[pixel,j] = LN(feats1) @ [Ww|Wk] + b  -> g_logits  grid (512, 1)
// MODE 2: out[b,j,n] = Wo^T @ agg^T + bo         -> d_out     grid (512, 2)
template <int MODE>
__global__ __launch_bounds__(256, 2) void gemm_mma(const float* __restrict__ feats,
                                                   const float* __restrict__ gamma,
                                                   const float* __restrict__ beta,
                                                   const float* __restrict__ Wsrc,
                                                   const float* __restrict__ bias,
                                                   float* __restrict__ out) {
    __shared__ uint32_t As[32 * PADM];   // [k][m], tf32 bits
    __shared__ uint32_t Bs[32 * PADM];   // [k][n], tf32 bits
    __shared__ float mean_s[128], rstd_s[128], gam_s[256], bet_s[256];

    const int t = threadIdx.x;
    const int lane = t & 31, wid = t >> 5;
    const int lk = lane & 3, lr = lane >> 2;
    const int wm = wid & 1, wn = wid >> 1;
    const int mb = wm * 64, nb = wn * 32;

    int m0 = 0, j0 = 0, b = 0, n0 = 0;
    if (MODE < 2) {
        m0 = blockIdx.x * 128; j0 = blockIdx.y * 128;
        b = m0 >> 15; n0 = m0 & (HW - 1);
    } else {
        n0 = blockIdx.x * 128; j0 = blockIdx.y * 128;
        b = n0 >> 15;
    }

    if (MODE < 2) {
        const int which = (MODE == 0) ? 1 : 0;
        if (t < 128) {
            mean_s[t] = g_mean[which * NPIX + m0 + t];
            rstd_s[t] = g_rstd[which * NPIX + m0 + t];
        }
        gam_s[t] = gamma[t];
        bet_s[t] = beta[t];
    }
    __syncthreads();

    float acc[4][4][4];
#pragma unroll
    for (int mi = 0; mi < 4; ++mi)
#pragma unroll
        for (int ni = 0; ni < 4; ++ni)
#pragma unroll
            for (int q = 0; q < 4; ++q) acc[mi][ni][q] = 0.f;

    const float* fb = (MODE < 2) ? feats + ((size_t)b << 23) + n0 : (const float*)0;

    for (int kc0 = 0; kc0 < 256; kc0 += 32) {
        // ---- fill A: As[k][m] ----
        if (MODE < 2) {
#pragma unroll
            for (int i = 0; i < 4; ++i) {
                const int idx = t + i * 256;
                const int c = idx >> 5, m4 = (idx & 31) << 2;
                const float4 v = *reinterpret_cast<const float4*>(
                    fb + ((size_t)(kc0 + c) << 15) + m4);
                const float ga = gam_s[kc0 + c], be = bet_s[kc0 + c];
                uint4 w;
                w.x = f2tf32((v.x - mean_s[m4 + 0]) * rstd_s[m4 + 0] * ga + be);
                w.y = f2tf32((v.y - mean_s[m4 + 1]) * rstd_s[m4 + 1] * ga + be);
                w.z = f2tf32((v.z - mean_s[m4 + 2]) * rstd_s[m4 + 2] * ga + be);
                w.w = f2tf32((v.w - mean_s[m4 + 3]) * rstd_s[m4 + 3] * ga + be);
                *reinterpret_cast<uint4*>(&As[c * PADM + m4]) = w;
            }
        } else {
#pragma unroll
            for (int i = 0; i < 4; ++i) {
                const int idx = t + i * 256;
                const int c = idx >> 5, m4 = (idx & 31) << 2;
                const float4 v = *reinterpret_cast<const float4*>(
                    Wsrc + (size_t)(kc0 + c) * 256 + j0 + m4);
                uint4 w;
                w.x = f2tf32(v.x); w.y = f2tf32(v.y);
                w.z = f2tf32(v.z); w.w = f2tf32(v.w);
                *reinterpret_cast<uint4*>(&As[c * PADM + m4]) = w;
            }
        }
        // ---- fill B: Bs[k][n] ----
        if (MODE == 0) {
#pragma unroll
            for (int i = 0; i < 4; ++i) {
                const int idx = t + i * 256;
                const int c = idx >> 5, m4 = (idx & 31) << 2;
                const float4 v = *reinterpret_cast<const float4*>(
                    Wsrc + (size_t)(kc0 + c) * 256 + j0 + m4);
                uint4 w;
                w.x = f2tf32(v.x); w.y = f2tf32(v.y);
                w.z = f2tf32(v.z); w.w = f2tf32(v.w);
                *reinterpret_cast<uint4*>(&Bs[c * PADM + m4]) = w;
            }
        } else if (MODE == 1) {
#pragma unroll
            for (int i = 0; i < 4; ++i) {
                const int idx = t + i * 256;
                const int c = idx >> 5, m4 = (idx & 31) << 2;
                const float4 v = *reinterpret_cast<const float4*>(
                    g_Wpad + (size_t)(kc0 + c) * 128 + m4);
                uint4 w;
                w.x = f2tf32(v.x); w.y = f2tf32(v.y);
                w.z = f2tf32(v.z); w.w = f2tf32(v.w);
                *reinterpret_cast<uint4*>(&Bs[c * PADM + m4]) = w;
            }
        } else {
            // B[k][n] = agg[n0+n][kc0+k]  (transpose in SMEM)
#pragma unroll
            for (int i = 0; i < 4; ++i) {
                const int idx = t + i * 256;
                const int n = idx & 127, kq = idx >> 7;     // kq 0..7
                const float4 v = *reinterpret_cast<const float4*>(
                    g_agg + ((size_t)(n0 + n) << 8) + kc0 + kq * 4);
                Bs[(kq * 4 + 0) * PADM + n] = f2tf32(v.x);
                Bs[(kq * 4 + 1) * PADM + n] = f2tf32(v.y);
                Bs[(kq * 4 + 2) * PADM + n] = f2tf32(v.z);
                Bs[(kq * 4 + 3) * PADM + n] = f2tf32(v.w);
            }
        }
        __syncthreads();

        // ---- 4 k8-steps of mma ----
#pragma unroll
        for (int ks = 0; ks < 4; ++ks) {
            const int kb = ks * 8;
            uint32_t a[4][4];
#pragma unroll
            for (int mi = 0; mi < 4; ++mi) {
                const uint32_t* Ab = &As[(kb + lk) * PADM + mb + 16 * mi + lr];
                a[mi][0] = Ab[0];
                a[mi][1] = Ab[8];
                a[mi][2] = Ab[4 * PADM];
                a[mi][3] = Ab[4 * PADM + 8];
            }
            uint32_t bf[4][2];
#pragma unroll
            for (int ni = 0; ni < 4; ++ni) {
                const uint32_t* Bb = &Bs[(kb + lk) * PADM + nb + 8 * ni + lr];
                bf[ni][0] = Bb[0];
                bf[ni][1] = Bb[4 * PADM];
            }
#pragma unroll
            for (int mi = 0; mi < 4; ++mi)
#pragma unroll
                for (int ni = 0; ni < 4; ++ni) {
                    asm volatile(
                        "mma.sync.aligned.m16n8k8.row.col.f32.tf32.tf32.f32 "
                        "{%0,%1,%2,%3}, {%4,%5,%6,%7}, {%8,%9}, {%0,%1,%2,%3};"
                        : "+f"(acc[mi][ni][0]), "+f"(acc[mi][ni][1]),
                          "+f"(acc[mi][ni][2]), "+f"(acc[mi][ni][3])
                        : "r"(a[mi][0]), "r"(a[mi][1]), "r"(a[mi][2]), "r"(a[mi][3]),
                          "r"(bf[ni][0]), "r"(bf[ni][1]));
                }
        }
        __syncthreads();
    }

    // ---- epilogue ----
    if (MODE < 2) {
        const float* bp = (MODE == 0) ? bias : g_bpad;
        const int LD = (MODE == 0) ? 256 : 128;
        float* base = (MODE == 0) ? g_value : g_logits;
        float bcol[4][2];
#pragma unroll
        for (int ni = 0; ni < 4; ++ni) {
            bcol[ni][0] = __ldg(bp + (MODE == 0 ? j0 : 0) + nb + 8 * ni + 2 * lk);
            bcol[ni][1] = __ldg(bp + (MODE == 0 ? j0 : 0) + nb + 8 * ni + 2 * lk + 1);
        }
#pragma unroll
        for (int mi = 0; mi < 4; ++mi) {
            const int m = m0 + mb + 16 * mi + lr;
#pragma unroll
            for (int ni = 0; ni < 4; ++ni) {
                const int cb = (MODE == 0 ? j0 : 0) + nb + 8 * ni + 2 * lk;
                float2 r0, r1;
                r0.x = acc[mi][ni][0] + bcol[ni][0];
                r0.y = acc[mi][ni][1] + bcol[ni][1];
                r1.x = acc[mi][ni][2] + bcol[ni][0];
                r1.y = acc[mi][ni][3] + bcol[ni][1];
                *reinterpret_cast<float2*>(base + (size_t)m * LD + cb) = r0;
                *reinterpret_cast<float2*>(base + (size_t)(m + 8) * LD + cb) = r1;
            }
        }
    } else {
        const int nbase = n0 & (HW - 1);
#pragma unroll
        for (int mi = 0; mi < 4; ++mi) {
            const int j = j0 + mb + 16 * mi + lr;
            const float br0 = __ldg(bias + j);
            const float br1 = __ldg(bias + j + 8);
            float* d0 = out + (((size_t)(b * CCH + j)) << 15) + nbase;
            float* d1 = out + (((size_t)(b * CCH + j + 8)) << 15) + nbase;
#pragma unroll
            for (int ni = 0; ni < 4; ++ni) {
                const int cb = nb + 8 * ni + 2 * lk;
                float2 r0, r1;
                r0.x = acc[mi][ni][0] + br0;
                r0.y = acc[mi][ni][1] + br0;
                r1.x = acc[mi][ni][2] + br1;
                r1.y = acc[mi][ni][3] + br1;
                *reinterpret_cast<float2*>(d0 + cb) = r0;
                *reinterpret_cast<float2*>(d1 + cb) = r1;
            }
        }
    }
}

// ---------------- K3b: fp32 keypoint offsets (precision-critical) -----------
// off[p] = LN(feats1)[pixel] . Wk[:,p] + bk[p];  kp = (anchor.x + off, anchor.y)
__global__ __launch_bounds__(256) void offs_kernel(const float* __restrict__ feats1,
                                                   const float* __restrict__ gamma,
                                                   const float* __restrict__ beta,
                                                   const float* __restrict__ Wk,
                                                   const float* __restrict__ bk,
                                                   const float* __restrict__ anchor,
                                                   float* __restrict__ kp_out) {
    __shared__ float wk_s[CCH * PPTS];    // [c][p], gamma folded in
    __shared__ float cA[PPTS];            // sum_c beta[c]*Wk[c][p]
    __shared__ float cB[PPTS];            // sum_c gamma[c]*Wk[c][p]
    const int t = threadIdx.x;

    for (int idx = t; idx < CCH * PPTS; idx += 256) {
        const int c = idx / PPTS;
        wk_s[idx] = gamma[c] * Wk[idx];
    }
    if (t < PPTS) {
        float a = 0.f, bsum = 0.f;
        for (int c = 0; c < CCH; ++c) {
            a    += beta[c] * Wk[c * PPTS + t];
            bsum += gamma[c] * Wk[c * PPTS + t];
        }
        cA[t] = a; cB[t] = bsum;
    }
    __syncthreads();

    const int pg = blockIdx.x * 256 + t;
    const int b = pg >> 15;
    const int n = pg & (HW - 1);
    const float* fb = feats1 + ((size_t)b << 23) + n;
    const float m = g_mean[pg];       // which=0 (feats1)
    const float r = g_rstd[pg];

    float acc[PPTS];
#pragma unroll
    for (int p = 0; p < PPTS; ++p) acc[p] = 0.f;

#pragma unroll 4
    for (int c = 0; c < CCH; ++c) {
        const float x = fb[(size_t)c << 15];
#pragma unroll
        for (int p = 0; p < PPTS; ++p)
            acc[p] = fmaf(x, wk_s[c * PPTS + p], acc[p]);
    }

    const float ax = anchor[2 * pg], ay = anchor[2 * pg + 1];
#pragma unroll
    for (int p = 0; p < PPTS; ++p) {
        // off = r*(S - m*B) + A + bk
        const float off = r * (acc[p] - m * cB[p]) + cA[p] + __ldg(bk + p);
        kp_out[((size_t)pg * PPTS + p) * 2]     = ax + off;
        kp_out[((size_t)pg * PPTS + p) * 2 + 1] = ay;
    }
}

// ---------------- K4: softmax over points (weights only) --------------------
__global__ __launch_bounds__(256) void wts_kernel() {
    const int pid = blockIdx.x * 256 + threadIdx.x;
    const float* row = g_logits + (size_t)pid * 128;
    float l[72];
#pragma unroll
    for (int j = 0; j < 72; ++j) l[j] = row[j];

#pragma unroll
    for (int g = 0; g < GRP; ++g) {
        float mx = l[g];
#pragma unroll
        for (int p = 1; p < PPTS; ++p) mx = fmaxf(mx, l[p * 8 + g]);
        float s = 0.f;
#pragma unroll
        for (int p = 0; p < PPTS; ++p) {
            float e = __expf(l[p * 8 + g] - mx);
            l[p * 8 + g] = e; s += e;
        }
        const float inv = 1.f / s;
#pragma unroll
        for (int p = 0; p < PPTS; ++p)
            g_wts[(size_t)pid * 72 + p * 8 + g] = l[p * 8 + g] * inv;
    }
}

// ---------------- K5: deformable bilinear gather (float4, 4 px/block) -------
__global__ __launch_bounds__(256) void agg_kernel(const float* __restrict__ kp) {
    __shared__ float w_s[4][72];
    __shared__ int   sxi[4][PPTS][2];
    __shared__ float sxy[4][PPTS][2];

    const int t = threadIdx.x;
    const int pg0 = blockIdx.x << 2;

    for (int idx = t; idx < 4 * 72; idx += 256) {
        const int lp = idx / 72, q = idx - lp * 72;
        w_s[lp][q] = g_wts[(size_t)(pg0 + lp) * 72 + q];
    }
    if (t < 4 * PPTS) {
        const int lp = t / PPTS, p = t - lp * PPTS;
        const size_t kidx = ((size_t)(pg0 + lp) * PPTS + p) * 2;
        const float x = kp[kidx] * (float)WWD - 0.5f;
        const float y = kp[kidx + 1] * (float)HH - 0.5f;
        const float xf = floorf(x), yf = floorf(y);
        sxi[lp][p][0] = (int)xf; sxi[lp][p][1] = (int)yf;
        sxy[lp][p][0] = x - xf;  sxy[lp][p][1] = y - yf;
    }
    __syncthreads();

    const int lp = t >> 6, ch = t & 63;
    const int c = ch << 2, g = ch >> 3;
    const int pg = pg0 + lp, b = pg >> 15;
    const float* vb = g_value + ((size_t)b << 23) + c;

    float ax = 0.f, ay = 0.f, az = 0.f, aw = 0.f;
#pragma unroll
    for (int p = 0; p < PPTS; ++p) {
        const int x0 = sxi[lp][p][0], y0 = sxi[lp][p][1];
        const float wx = sxy[lp][p][0], wy = sxy[lp][p][1];
        const float wp = w_s[lp][p * 8 + g];
        const bool yv0 = (y0 >= 0) & (y0 < HH);
        const bool yv1 = (y0 + 1 >= 0) & (y0 + 1 < HH);
        const bool xv0 = (x0 >= 0) & (x0 < WWD);
        const bool xv1 = (x0 + 1 >= 0) & (x0 + 1 < WWD);
        float4 v00 = {0, 0, 0, 0}, v01 = {0, 0, 0, 0}, v10 = {0, 0, 0, 0}, v11 = {0, 0, 0, 0};
        if (yv0 && xv0) v00 = *reinterpret_cast<const float4*>(vb + ((size_t)(y0 * WWD + x0) << 8));
        if (yv0 && xv1) v01 = *reinterpret_cast<const float4*>(vb + ((size_t)(y0 * WWD + x0 + 1) << 8));
        if (yv1 && xv0) v10 = *reinterpret_cast<const float4*>(vb + ((size_t)((y0 + 1) * WWD + x0) << 8));
        if (yv1 && xv1) v11 = *reinterpret_cast<const float4*>(vb + ((size_t)((y0 + 1) * WWD + x0 + 1) << 8));
        const float w00 = (1.f - wx) * (1.f - wy), w01 = wx * (1.f - wy);
        const float w10 = (1.f - wx) * wy,         w11 = wx * wy;
        ax = fmaf(wp, v00.x * w00 + v01.x * w01 + v10.x * w10 + v11.x * w11, ax);
        ay = fmaf(wp, v00.y * w00 + v01.y * w01 + v10.y * w10 + v11.y * w11, ay);
        az = fmaf(wp, v00.z * w00 + v01.z * w01 + v10.z * w10 + v11.z * w11, az);
        aw = fmaf(wp, v00.w * w00 + v01.w * w01 + v10.w * w10 + v11.w * w11, aw);
    }
    float4 r; r.x = ax; r.y = ay; r.z = az; r.w = aw;
    *reinterpret_cast<float4*>(g_agg + ((size_t)pg << 8) + c) = r;
}

// ---------------- launch -----------------------------------------------------
extern "C" void kernel_launch(void* const* d_in, const int* in_sizes, int n_in,
                              void* d_out, int out_size) {
    const float* feats1 = (const float*)d_in[0];
    const float* feats2 = (const float*)d_in[1];
    const float* anchor = (const float*)d_in[2];
    const float* n1g = (const float*)d_in[3];
    const float* n1b = (const float*)d_in[4];
    const float* n2g = (const float*)d_in[5];
    const float* n2b = (const float*)d_in[6];
    const float* Wv  = (const float*)d_in[7];
    const float* bv  = (const float*)d_in[8];
    const float* Ww  = (const float*)d_in[9];
    const float* bw  = (const float*)d_in[10];
    const float* Wk  = (const float*)d_in[11];
    const float* bk  = (const float*)d_in[12];
    const float* Wo  = (const float*)d_in[13];
    const float* bo  = (const float*)d_in[14];

    float* out    = (float*)d_out;
    float* kp_out = out + (size_t)16777216;   // B*C*H*W

    stats_kernel<<<dim3(NPIX / 128, 2), 128>>>(feats1, feats2);
    prep_kernel<<<128, 256>>>(Ww, bw, Wk, bk);
    gemm_mma<0><<<dim3(512, 2), 256>>>(feats2, n2g, n2b, Wv, bv, nullptr);
    gemm_mma<1><<<dim3(512, 1), 256>>>(feats1, n1g, n1b, nullptr, nullptr, nullptr);
    offs_kernel<<<NPIX / 256, 256>>>(feats1, n1g, n1b, Wk, bk, anchor, kp_out);
    wts_kernel<<<NPIX / 256, 256>>>();
    agg_kernel<<<NPIX / 4, 256>>>(kp_out);
    gemm_mma<2><<<dim3(512, 2), 256>>>(nullptr, nullptr, nullptr, Wo, bo, out);
}

// round 6
// speedup vs baseline: 2.1151x; 1.1526x over previous
#include <cuda_runtime.h>
#include <cuda_fp16.h>
#include <cstdint>
#include <math.h>

// Problem dims
#define HW   32768
#define CCH  256
#define HH   128
#define WWD  256
#define NPIX 65536      // B * HW
#define PPTS 9
#define GRP  8

#define PADM 136        // SMEM row stride (floats); conflict-free frag loads
#define KCH  64         // K-chunk depth

// ---------------- scratch (static device globals; no allocation) ------------
__device__ float  g_mean[2 * NPIX];
__device__ float  g_rstd[2 * NPIX];
__device__ __half g_value[(size_t)NPIX * CCH];    // (pixel, j) fp16, 32 MiB
__device__ float  g_logits[(size_t)NPIX * 128];   // padded; cols 0..71 consumed
__device__ __half g_agg[(size_t)NPIX * CCH];      // fp16, 32 MiB
__device__ float  g_Wpad[CCH * 128];              // [k][j] = [Ww | Wk | 0]
__device__ float  g_bpad[128];

__device__ __forceinline__ uint32_t f2tf32(float f) {
    uint32_t r;
    asm("cvt.rna.tf32.f32 %0, %1;" : "=r"(r) : "f"(f));
    return r;
}

// ---------------- K1: per-pixel LN stats (float4, 4 px/thread) --------------
__global__ __launch_bounds__(128) void stats_kernel(const float* __restrict__ f1,
                                                    const float* __restrict__ f2) {
    const int t = threadIdx.x;
    const int pg0 = (blockIdx.x * 128 + t) * 4;
    const int which = blockIdx.y;
    const float* f = which ? f2 : f1;
    const int b = pg0 >> 15;
    const int n = pg0 & (HW - 1);
    const float* base = f + ((size_t)b << 23) + n;
    float4 s = {0, 0, 0, 0}, s2 = {0, 0, 0, 0};
#pragma unroll 4
    for (int c = 0; c < CCH; ++c) {
        const float4 v = *reinterpret_cast<const float4*>(base + ((size_t)c << 15));
        s.x += v.x; s.y += v.y; s.z += v.z; s.w += v.w;
        s2.x += v.x * v.x; s2.y += v.y * v.y; s2.z += v.z * v.z; s2.w += v.w * v.w;
    }
    const float inv = 1.f / 256.f;
    float m[4] = {s.x * inv, s.y * inv, s.z * inv, s.w * inv};
    float q[4] = {s2.x * inv, s2.y * inv, s2.z * inv, s2.w * inv};
#pragma unroll
    for (int i = 0; i < 4; ++i) {
        g_mean[which * NPIX + pg0 + i] = m[i];
        g_rstd[which * NPIX + pg0 + i] = rsqrtf(q[i] - m[i] * m[i] + 1e-5f);
    }
}

// ---------------- K2: build padded [Ww|Wk] weight + bias --------------------
__global__ void prep_kernel(const float* __restrict__ Ww, const float* __restrict__ bw,
                            const float* __restrict__ Wk, const float* __restrict__ bk) {
    int idx = blockIdx.x * 256 + threadIdx.x;       // 128*256 = 32768
    if (idx < CCH * 128) {
        int c = idx >> 7, j = idx & 127;
        float v = 0.f;
        if (j < 72)      v = Ww[c * 72 + j];
        else if (j < 81) v = Wk[c * 9 + (j - 72)];
        g_Wpad[idx] = v;
    }
    if (idx < 128)
        g_bpad[idx] = (idx < 72) ? bw[idx] : ((idx < 81) ? bk[idx - 72] : 0.f);
}

// ---------------- K3: tf32 mma.sync GEMM (3 modes), K-chunk 64 --------------
// MODE 0: C[pixel,j] = LN(feats2) @ Wv + bv      -> g_value(half)  grid (512, 2)
// MODE 1: C[pixel,j] = LN(feats1) @ [Ww|Wk] + b  -> g_logits       grid (512, 1)
// MODE 2: out[b,j,n] = Wo^T @ agg^T + bo         -> d_out          grid (512, 2)
template <int MODE>
__global__ __launch_bounds__(256, 2) void gemm_mma(const float* __restrict__ feats,
                                                   const float* __restrict__ gamma,
                                                   const float* __restrict__ beta,
                                                   const float* __restrict__ Wsrc,
                                                   const float* __restrict__ bias,
                                                   float* __restrict__ out) {
    extern __shared__ char smem_raw[];
    uint32_t* As = reinterpret_cast<uint32_t*>(smem_raw);             // [KCH][PADM]
    uint32_t* Bs = As + KCH * PADM;                                   // [KCH][PADM]
    float* mean_s = reinterpret_cast<float*>(Bs + KCH * PADM);
    float* rstd_s = mean_s + 128;
    float* gam_s  = rstd_s + 128;
    float* bet_s  = gam_s + 256;

    const int t = threadIdx.x;
    const int lane = t & 31, wid = t >> 5;
    const int lk = lane & 3, lr = lane >> 2;
    const int wm = wid & 1, wn = wid >> 1;
    const int mb = wm * 64, nb = wn * 32;

    int m0 = 0, j0 = 0, b = 0, n0 = 0;
    if (MODE < 2) {
        m0 = blockIdx.x * 128; j0 = blockIdx.y * 128;
        b = m0 >> 15; n0 = m0 & (HW - 1);
    } else {
        n0 = blockIdx.x * 128; j0 = blockIdx.y * 128;
        b = n0 >> 15;
    }

    if (MODE < 2) {
        const int which = (MODE == 0) ? 1 : 0;
        if (t < 128) {
            mean_s[t] = g_mean[which * NPIX + m0 + t];
            rstd_s[t] = g_rstd[which * NPIX + m0 + t];
        }
        gam_s[t] = gamma[t];
        bet_s[t] = beta[t];
    }
    __syncthreads();

    float acc[4][4][4];
#pragma unroll
    for (int mi = 0; mi < 4; ++mi)
#pragma unroll
        for (int ni = 0; ni < 4; ++ni)
#pragma unroll
            for (int q = 0; q < 4; ++q) acc[mi][ni][q] = 0.f;

    const float* fb = (MODE < 2) ? feats + ((size_t)b << 23) + n0 : (const float*)0;

    for (int kc0 = 0; kc0 < 256; kc0 += KCH) {
        // ---- fill A: As[k][m] (8 float4 per thread) ----
        if (MODE < 2) {
#pragma unroll
            for (int i = 0; i < 8; ++i) {
                const int idx = t + i * 256;
                const int c = idx >> 5, m4 = (idx & 31) << 2;
                const float4 v = *reinterpret_cast<const float4*>(
                    fb + ((size_t)(kc0 + c) << 15) + m4);
                const float ga = gam_s[kc0 + c], be = bet_s[kc0 + c];
                uint4 w;
                w.x = f2tf32((v.x - mean_s[m4 + 0]) * rstd_s[m4 + 0] * ga + be);
                w.y = f2tf32((v.y - mean_s[m4 + 1]) * rstd_s[m4 + 1] * ga + be);
                w.z = f2tf32((v.z - mean_s[m4 + 2]) * rstd_s[m4 + 2] * ga + be);
                w.w = f2tf32((v.w - mean_s[m4 + 3]) * rstd_s[m4 + 3] * ga + be);
                *reinterpret_cast<uint4*>(&As[c * PADM + m4]) = w;
            }
        } else {
#pragma unroll
            for (int i = 0; i < 8; ++i) {
                const int idx = t + i * 256;
                const int c = idx >> 5, m4 = (idx & 31) << 2;
                const float4 v = *reinterpret_cast<const float4*>(
                    Wsrc + (size_t)(kc0 + c) * 256 + j0 + m4);
                uint4 w;
                w.x = f2tf32(v.x); w.y = f2tf32(v.y);
                w.z = f2tf32(v.z); w.w = f2tf32(v.w);
                *reinterpret_cast<uint4*>(&As[c * PADM + m4]) = w;
            }
        }
        // ---- fill B: Bs[k][n] ----
        if (MODE == 0) {
#pragma unroll
            for (int i = 0; i < 8; ++i) {
                const int idx = t + i * 256;
                const int c = idx >> 5, m4 = (idx & 31) << 2;
                const float4 v = *reinterpret_cast<const float4*>(
                    Wsrc + (size_t)(kc0 + c) * 256 + j0 + m4);
                uint4 w;
                w.x = f2tf32(v.x); w.y = f2tf32(v.y);
                w.z = f2tf32(v.z); w.w = f2tf32(v.w);
                *reinterpret_cast<uint4*>(&Bs[c * PADM + m4]) = w;
            }
        } else if (MODE == 1) {
#pragma unroll
            for (int i = 0; i < 8; ++i) {
                const int idx = t + i * 256;
                const int c = idx >> 5, m4 = (idx & 31) << 2;
                const float4 v = *reinterpret_cast<const float4*>(
                    g_Wpad + (size_t)(kc0 + c) * 128 + m4);
                uint4 w;
                w.x = f2tf32(v.x); w.y = f2tf32(v.y);
                w.z = f2tf32(v.z); w.w = f2tf32(v.w);
                *reinterpret_cast<uint4*>(&Bs[c * PADM + m4]) = w;
            }
        } else {
            // B[k][n] = agg[n0+n][kc0+k]  (half source, transpose in SMEM)
#pragma unroll
            for (int i = 0; i < 8; ++i) {
                const int idx = t + i * 256;              // 0..2047
                const int n = idx & 127, kq = idx >> 7;   // kq 0..15
                const uint2 raw = *reinterpret_cast<const uint2*>(
                    g_agg + ((size_t)(n0 + n) << 8) + kc0 + kq * 4);
                const __half2 h0 = *reinterpret_cast<const __half2*>(&raw.x);
                const __half2 h1 = *reinterpret_cast<const __half2*>(&raw.y);
                const float2 f0 = __half22float2(h0);
                const float2 f1 = __half22float2(h1);
                Bs[(kq * 4 + 0) * PADM + n] = f2tf32(f0.x);
                Bs[(kq * 4 + 1) * PADM + n] = f2tf32(f0.y);
                Bs[(kq * 4 + 2) * PADM + n] = f2tf32(f1.x);
                Bs[(kq * 4 + 3) * PADM + n] = f2tf32(f1.y);
            }
        }
        __syncthreads();

        // ---- 8 k8-steps of mma (each step consumes 8 k: lk and lk+4 rows) ----
#pragma unroll
        for (int ks = 0; ks < KCH / 8; ++ks) {
            const int kb = ks * 8;
            uint32_t a[4][4];
#pragma unroll
            for (int mi = 0; mi < 4; ++mi) {
                const uint32_t* Ab = &As[(kb + lk) * PADM + mb + 16 * mi + lr];
                a[mi][0] = Ab[0];
                a[mi][1] = Ab[8];
                a[mi][2] = Ab[4 * PADM];
                a[mi][3] = Ab[4 * PADM + 8];
            }
            uint32_t bf[4][2];
#pragma unroll
            for (int ni = 0; ni < 4; ++ni) {
                const uint32_t* Bb = &Bs[(kb + lk) * PADM + nb + 8 * ni + lr];
                bf[ni][0] = Bb[0];
                bf[ni][1] = Bb[4 * PADM];
            }
#pragma unroll
            for (int mi = 0; mi < 4; ++mi)
#pragma unroll
                for (int ni = 0; ni < 4; ++ni) {
                    asm volatile(
                        "mma.sync.aligned.m16n8k8.row.col.f32.tf32.tf32.f32 "
                        "{%0,%1,%2,%3}, {%4,%5,%6,%7}, {%8,%9}, {%0,%1,%2,%3};"
                        : "+f"(acc[mi][ni][0]), "+f"(acc[mi][ni][1]),
                          "+f"(acc[mi][ni][2]), "+f"(acc[mi][ni][3])
                        : "r"(a[mi][0]), "r"(a[mi][1]), "r"(a[mi][2]), "r"(a[mi][3]),
                          "r"(bf[ni][0]), "r"(bf[ni][1]));
                }
        }
        __syncthreads();
    }

    // ---- epilogue ----
    if (MODE == 0) {
        float bcol[4][2];
#pragma unroll
        for (int ni = 0; ni < 4; ++ni) {
            bcol[ni][0] = __ldg(bias + j0 + nb + 8 * ni + 2 * lk);
            bcol[ni][1] = __ldg(bias + j0 + nb + 8 * ni + 2 * lk + 1);
        }
#pragma unroll
        for (int mi = 0; mi < 4; ++mi) {
            const int m = m0 + mb + 16 * mi + lr;
#pragma unroll
            for (int ni = 0; ni < 4; ++ni) {
                const int cb = j0 + nb + 8 * ni + 2 * lk;
                const __half2 h0 = __floats2half2_rn(acc[mi][ni][0] + bcol[ni][0],
                                                     acc[mi][ni][1] + bcol[ni][1]);
                const __half2 h1 = __floats2half2_rn(acc[mi][ni][2] + bcol[ni][0],
                                                     acc[mi][ni][3] + bcol[ni][1]);
                *reinterpret_cast<__half2*>(g_value + (size_t)m * 256 + cb) = h0;
                *reinterpret_cast<__half2*>(g_value + (size_t)(m + 8) * 256 + cb) = h1;
            }
        }
    } else if (MODE == 1) {
        float bcol[4][2];
#pragma unroll
        for (int ni = 0; ni < 4; ++ni) {
            bcol[ni][0] = g_bpad[nb + 8 * ni + 2 * lk];
            bcol[ni][1] = g_bpad[nb + 8 * ni + 2 * lk + 1];
        }
#pragma unroll
        for (int mi = 0; mi < 4; ++mi) {
            const int m = m0 + mb + 16 * mi + lr;
#pragma unroll
            for (int ni = 0; ni < 4; ++ni) {
                const int cb = nb + 8 * ni + 2 * lk;
                float2 r0, r1;
                r0.x = acc[mi][ni][0] + bcol[ni][0];
                r0.y = acc[mi][ni][1] + bcol[ni][1];
                r1.x = acc[mi][ni][2] + bcol[ni][0];
                r1.y = acc[mi][ni][3] + bcol[ni][1];
                *reinterpret_cast<float2*>(g_logits + (size_t)m * 128 + cb) = r0;
                *reinterpret_cast<float2*>(g_logits + (size_t)(m + 8) * 128 + cb) = r1;
            }
        }
    } else {
        const int nbase = n0 & (HW - 1);
#pragma unroll
        for (int mi = 0; mi < 4; ++mi) {
            const int j = j0 + mb + 16 * mi + lr;
            const float br0 = __ldg(bias + j);
            const float br1 = __ldg(bias + j + 8);
            float* d0 = out + (((size_t)(b * CCH + j)) << 15) + nbase;
            float* d1 = out + (((size_t)(b * CCH + j + 8)) << 15) + nbase;
#pragma unroll
            for (int ni = 0; ni < 4; ++ni) {
                const int cb = nb + 8 * ni + 2 * lk;
                float2 r0, r1;
                r0.x = acc[mi][ni][0] + br0;
                r0.y = acc[mi][ni][1] + br0;
                r1.x = acc[mi][ni][2] + br1;
                r1.y = acc[mi][ni][3] + br1;
                *reinterpret_cast<float2*>(d0 + cb) = r0;
                *reinterpret_cast<float2*>(d1 + cb) = r1;
            }
        }
    }
}

// ---------------- K3b: fp32 keypoint offsets (precision-critical) -----------
__global__ __launch_bounds__(256) void offs_kernel(const float* __restrict__ feats1,
                                                   const float* __restrict__ gamma,
                                                   const float* __restrict__ beta,
                                                   const float* __restrict__ Wk,
                                                   const float* __restrict__ bk,
                                                   const float* __restrict__ anchor,
                                                   float* __restrict__ kp_out) {
    __shared__ float wk_s[CCH * PPTS];    // [c][p], gamma folded in
    __shared__ float cA[PPTS];
    __shared__ float cB[PPTS];
    const int t = threadIdx.x;

    for (int idx = t; idx < CCH * PPTS; idx += 256) {
        const int c = idx / PPTS;
        wk_s[idx] = gamma[c] * Wk[idx];
    }
    if (t < PPTS) {
        float a = 0.f, bsum = 0.f;
        for (int c = 0; c < CCH; ++c) {
            a    += beta[c] * Wk[c * PPTS + t];
            bsum += gamma[c] * Wk[c * PPTS + t];
        }
        cA[t] = a; cB[t] = bsum;
    }
    __syncthreads();

    const int pg = blockIdx.x * 256 + t;
    const int b = pg >> 15;
    const int n = pg & (HW - 1);
    const float* fb = feats1 + ((size_t)b << 23) + n;
    const float m = g_mean[pg];
    const float r = g_rstd[pg];

    float acc[PPTS];
#pragma unroll
    for (int p = 0; p < PPTS; ++p) acc[p] = 0.f;

#pragma unroll 4
    for (int c = 0; c < CCH; ++c) {
        const float x = fb[(size_t)c << 15];
#pragma unroll
        for (int p = 0; p < PPTS; ++p)
            acc[p] = fmaf(x, wk_s[c * PPTS + p], acc[p]);
    }

    const float ax = anchor[2 * pg], ay = anchor[2 * pg + 1];
#pragma unroll
    for (int p = 0; p < PPTS; ++p) {
        const float off = r * (acc[p] - m * cB[p]) + cA[p] + __ldg(bk + p);
        kp_out[((size_t)pg * PPTS + p) * 2]     = ax + off;
        kp_out[((size_t)pg * PPTS + p) * 2 + 1] = ay;
    }
}

// ---------------- K5: fused softmax + deformable gather (4 px/block) --------
__global__ __launch_bounds__(256) void agg_kernel(const float* __restrict__ kp) {
    __shared__ float w_s[4][72];
    __shared__ int   sxi[4][PPTS][2];
    __shared__ float sxy[4][PPTS][2];

    const int t = threadIdx.x;
    const int pg0 = blockIdx.x << 2;

    // warp 0: inline softmax (one thread per (pixel, group))
    if (t < 32) {
        const int lp = t >> 3, g = t & 7;
        const float* row = g_logits + (size_t)(pg0 + lp) * 128 + g;
        float l[PPTS];
        float mx = -1e30f;
#pragma unroll
        for (int p = 0; p < PPTS; ++p) { l[p] = row[p * 8]; mx = fmaxf(mx, l[p]); }
        float s = 0.f;
#pragma unroll
        for (int p = 0; p < PPTS; ++p) { l[p] = __expf(l[p] - mx); s += l[p]; }
        const float inv = 1.f / s;
#pragma unroll
        for (int p = 0; p < PPTS; ++p) w_s[lp][p * 8 + g] = l[p] * inv;
    }
    // threads [64,100): keypoint prep
    if (t >= 64 && t < 64 + 4 * PPTS) {
        const int idx = t - 64;
        const int lp = idx / PPTS, p = idx - lp * PPTS;
        const size_t kidx = ((size_t)(pg0 + lp) * PPTS + p) * 2;
        const float x = kp[kidx] * (float)WWD - 0.5f;
        const float y = kp[kidx + 1] * (float)HH - 0.5f;
        const float xf = floorf(x), yf = floorf(y);
        sxi[lp][p][0] = (int)xf; sxi[lp][p][1] = (int)yf;
        sxy[lp][p][0] = x - xf;  sxy[lp][p][1] = y - yf;
    }
    __syncthreads();

    const int lp = t >> 6, ch = t & 63;
    const int c = ch << 2, g = ch >> 3;
    const int pg = pg0 + lp, b = pg >> 15;
    const __half* vb = g_value + ((size_t)b << 23) + c;

    float ax = 0.f, ay = 0.f, az = 0.f, aw = 0.f;
#pragma unroll
    for (int p = 0; p < PPTS; ++p) {
        const int x0 = sxi[lp][p][0], y0 = sxi[lp][p][1];
        const float wx = sxy[lp][p][0], wy = sxy[lp][p][1];
        const float wp = w_s[lp][p * 8 + g];
        const bool yv0 = (y0 >= 0) & (y0 < HH);
        const bool yv1 = (y0 + 1 >= 0) & (y0 + 1 < HH);
        const bool xv0 = (x0 >= 0) & (x0 < WWD);
        const bool xv1 = (x0 + 1 >= 0) & (x0 + 1 < WWD);
        float2 v00a = {0, 0}, v00b = {0, 0}, v01a = {0, 0}, v01b = {0, 0};
        float2 v10a = {0, 0}, v10b = {0, 0}, v11a = {0, 0}, v11b = {0, 0};
        if (yv0 && xv0) {
            const uint2 raw = *reinterpret_cast<const uint2*>(vb + ((size_t)(y0 * WWD + x0) << 8));
            v00a = __half22float2(*reinterpret_cast<const __half2*>(&raw.x));
            v00b = __half22float2(*reinterpret_cast<const __half2*>(&raw.y));
        }
        if (yv0 && xv1) {
            const uint2 raw = *reinterpret_cast<const uint2*>(vb + ((size_t)(y0 * WWD + x0 + 1) << 8));
            v01a = __half22float2(*reinterpret_cast<const __half2*>(&raw.x));
            v01b = __half22float2(*reinterpret_cast<const __half2*>(&raw.y));
        }
        if (yv1 && xv0) {
            const uint2 raw = *reinterpret_cast<const uint2*>(vb + ((size_t)((y0 + 1) * WWD + x0) << 8));
            v10a = __half22float2(*reinterpret_cast<const __half2*>(&raw.x));
            v10b = __half22float2(*reinterpret_cast<const __half2*>(&raw.y));
        }
        if (yv1 && xv1) {
            const uint2 raw = *reinterpret_cast<const uint2*>(vb + ((size_t)((y0 + 1) * WWD + x0 + 1) << 8));
            v11a = __half22float2(*reinterpret_cast<const __half2*>(&raw.x));
            v11b = __half22float2(*reinterpret_cast<const __half2*>(&raw.y));
        }
        const float w00 = (1.f - wx) * (1.f - wy), w01 = wx * (1.f - wy);
        const float w10 = (1.f - wx) * wy,         w11 = wx * wy;
        ax = fmaf(wp, v00a.x * w00 + v01a.x * w01 + v10a.x * w10 + v11a.x * w11, ax);
        ay = fmaf(wp, v00a.y * w00 + v01a.y * w01 + v10a.y * w10 + v11a.y * w11, ay);
        az = fmaf(wp, v00b.x * w00 + v01b.x * w01 + v10b.x * w10 + v11b.x * w11, az);
        aw = fmaf(wp, v00b.y * w00 + v01b.y * w01 + v10b.y * w10 + v11b.y * w11, aw);
    }
    const __half2 h0 = __floats2half2_rn(ax, ay);
    const __half2 h1 = __floats2half2_rn(az, aw);
    uint2 st;
    st.x = *reinterpret_cast<const uint32_t*>(&h0);
    st.y = *reinterpret_cast<const uint32_t*>(&h1);
    *reinterpret_cast<uint2*>(g_agg + ((size_t)pg << 8) + c) = st;
}

// ---------------- launch -----------------------------------------------------
#define GEMM_SMEM ((2 * KCH * PADM + 768) * 4)

extern "C" void kernel_launch(void* const* d_in, const int* in_sizes, int n_in,
                              void* d_out, int out_size) {
    const float* feats1 = (const float*)d_in[0];
    const float* feats2 = (const float*)d_in[1];
    const float* anchor = (const float*)d_in[2];
    const float* n1g = (const float*)d_in[3];
    const float* n1b = (const float*)d_in[4];
    const float* n2g = (const float*)d_in[5];
    const float* n2b = (const float*)d_in[6];
    const float* Wv  = (const float*)d_in[7];
    const float* bv  = (const float*)d_in[8];
    const float* Ww  = (const float*)d_in[9];
    const float* bw  = (const float*)d_in[10];
    const float* Wk  = (const float*)d_in[11];
    const float* bk  = (const float*)d_in[12];
    const float* Wo  = (const float*)d_in[13];
    const float* bo  = (const float*)d_in[14];

    float* out    = (float*)d_out;
    float* kp_out = out + (size_t)16777216;   // B*C*H*W

    cudaFuncSetAttribute(gemm_mma<0>, cudaFuncAttributeMaxDynamicSharedMemorySize, GEMM_SMEM);
    cudaFuncSetAttribute(gemm_mma<1>, cudaFuncAttributeMaxDynamicSharedMemorySize, GEMM_SMEM);
    cudaFuncSetAttribute(gemm_mma<2>, cudaFuncAttributeMaxDynamicSharedMemorySize, GEMM_SMEM);

    stats_kernel<<<dim3(NPIX / 512, 2), 128>>>(feats1, feats2);
    prep_kernel<<<128, 256>>>(Ww, bw, Wk, bk);
    gemm_mma<0><<<dim3(512, 2), 256, GEMM_SMEM>>>(feats2, n2g, n2b, Wv, bv, nullptr);
    gemm_mma<1><<<dim3(512, 1), 256, GEMM_SMEM>>>(feats1, n1g, n1b, nullptr, nullptr, nullptr);
    offs_kernel<<<NPIX / 256, 256>>>(feats1, n1g, n1b, Wk, bk, anchor, kp_out);
    agg_kernel<<<NPIX / 4, 256>>>(kp_out);
    gemm_mma<2><<<dim3(512, 2), 256, GEMM_SMEM>>>(nullptr, nullptr, nullptr, Wo, bo, out);
}

// round 8
// speedup vs baseline: 2.2692x; 1.0729x over previous
#include <cuda_runtime.h>
#include <cuda_fp16.h>
#include <cstdint>
#include <math.h>

// Problem dims
#define HW   32768
#define CCH  256
#define HH   128
#define WWD  256
#define NPIX 65536      // B * HW
#define PPTS 9
#define GRP  8

#define PADM 136        // tf32 SMEM row stride (floats)
#define PADK 40         // f16 SMEM row stride (halves)

// ---------------- scratch (static device globals; no allocation) ------------
__device__ float  g_mean[2 * NPIX];
__device__ float  g_rstd[2 * NPIX];
__device__ __half g_value[(size_t)NPIX * CCH];    // (pixel, j) fp16
__device__ float  g_logits[(size_t)NPIX * 128];   // cols 0..71 consumed
__device__ __half g_agg[(size_t)NPIX * CCH];      // fp16
__device__ float  g_Wpad[CCH * 128];              // [c][j] = [Ww | Wk | 0]
__device__ float  g_bpad[128];
__device__ float  g_W2v[CCH * 256];               // tf32(gamma2*Wv) [c][j]
__device__ float  g_W2w[CCH * 128];               // tf32(gamma1*Wpad) [c][j]
__device__ __half g_WoT[256 * 256];               // Wo^T fp16 [j][c]
__device__ float  g_uv[256], g_vv[256];           // mode0 epilogue vectors
__device__ float  g_uw[128], g_vw[128];           // mode1 epilogue vectors

__device__ __forceinline__ uint32_t f2tf32(float f) {
    uint32_t r;
    asm("cvt.rna.tf32.f32 %0, %1;" : "=r"(r) : "f"(f));
    return r;
}
__device__ __forceinline__ uint32_t smem_u32(const void* p) {
    uint32_t a;
    asm("{ .reg .u64 t; cvta.to.shared.u64 t, %1; cvt.u32.u64 %0, t; }" : "=r"(a) : "l"(p));
    return a;
}
#define CP16(dst, src) \
    asm volatile("cp.async.cg.shared.global [%0], [%1], 16;" :: "r"(dst), "l"(src))
#define CPCOMMIT() asm volatile("cp.async.commit_group;" ::)
#define CPWAIT1()  asm volatile("cp.async.wait_group 1;" ::)

// ---------------- K1a: feats2 LN stats (4 px/thread) ------------------------
__global__ __launch_bounds__(128) void stats2_kernel(const float* __restrict__ f2) {
    const int t = threadIdx.x;
    const int pg0 = (blockIdx.x * 128 + t) * 4;
    const int b = pg0 >> 15;
    const int n = pg0 & (HW - 1);
    const float* base = f2 + ((size_t)b << 23) + n;
    float4 s = {0, 0, 0, 0}, s2 = {0, 0, 0, 0};
#pragma unroll 4
    for (int c = 0; c < CCH; ++c) {
        const float4 v = *reinterpret_cast<const float4*>(base + ((size_t)c << 15));
        s.x += v.x; s.y += v.y; s.z += v.z; s.w += v.w;
        s2.x += v.x * v.x; s2.y += v.y * v.y; s2.z += v.z * v.z; s2.w += v.w * v.w;
    }
    const float inv = 1.f / 256.f;
    float m[4] = {s.x * inv, s.y * inv, s.z * inv, s.w * inv};
    float q[4] = {s2.x * inv, s2.y * inv, s2.z * inv, s2.w * inv};
#pragma unroll
    for (int i = 0; i < 4; ++i) {
        g_mean[NPIX + pg0 + i] = m[i];
        g_rstd[NPIX + pg0 + i] = rsqrtf(q[i] - m[i] * m[i] + 1e-5f);
    }
}

// ---------------- K1b: feats1 LN stats + fp32 keypoint offsets (2 px/thread)
__global__ __launch_bounds__(128) void stats1_kernel(const float* __restrict__ f1,
                                                     const float* __restrict__ gamma,
                                                     const float* __restrict__ beta,
                                                     const float* __restrict__ Wk,
                                                     const float* __restrict__ bk,
                                                     const float* __restrict__ anchor,
                                                     float* __restrict__ kp_out) {
    __shared__ float wk_s[CCH * PPTS];
    __shared__ float cA[PPTS], cB[PPTS], bk_s[PPTS];
    const int t = threadIdx.x;

    for (int idx = t; idx < CCH * PPTS; idx += 128) {
        const int c = idx / PPTS;
        wk_s[idx] = gamma[c] * Wk[idx];
    }
    if (t < PPTS) {
        float a = 0.f, bs = 0.f;
        for (int c = 0; c < CCH; ++c) {
            a  += beta[c]  * Wk[c * PPTS + t];
            bs += gamma[c] * Wk[c * PPTS + t];
        }
        cA[t] = a; cB[t] = bs; bk_s[t] = bk[t];
    }
    __syncthreads();

    const int pg0 = (blockIdx.x * 128 + t) * 2;
    const int b = pg0 >> 15;
    const int n = pg0 & (HW - 1);
    const float* base = f1 + ((size_t)b << 23) + n;

    float2 s = {0, 0}, s2 = {0, 0};
    float o0[PPTS], o1[PPTS];
#pragma unroll
    for (int p = 0; p < PPTS; ++p) { o0[p] = 0.f; o1[p] = 0.f; }

    for (int c = 0; c < CCH; ++c) {
        const float2 v = *reinterpret_cast<const float2*>(base + ((size_t)c << 15));
        s.x += v.x; s.y += v.y;
        s2.x += v.x * v.x; s2.y += v.y * v.y;
#pragma unroll
        for (int p = 0; p < PPTS; ++p) {
            const float w = wk_s[c * PPTS + p];
            o0[p] = fmaf(v.x, w, o0[p]);
            o1[p] = fmaf(v.y, w, o1[p]);
        }
    }
    const float inv = 1.f / 256.f;
#pragma unroll
    for (int i = 0; i < 2; ++i) {
        const int pg = pg0 + i;
        const float m = (i ? s.y : s.x) * inv;
        const float q = (i ? s2.y : s2.x) * inv;
        const float r = rsqrtf(q - m * m + 1e-5f);
        g_mean[pg] = m;
        g_rstd[pg] = r;
        const float ax = anchor[2 * pg], ay = anchor[2 * pg + 1];
        const float* oo = i ? o1 : o0;
#pragma unroll
        for (int p = 0; p < PPTS; ++p) {
            const float off = r * (oo[p] - m * cB[p]) + cA[p] + bk_s[p];
            kp_out[((size_t)pg * PPTS + p) * 2]     = ax + off;
            kp_out[((size_t)pg * PPTS + p) * 2 + 1] = ay;
        }
    }
}

// ---------------- K2: build padded [Ww|Wk] + bias ---------------------------
__global__ void prep_kernel(const float* __restrict__ Ww, const float* __restrict__ bw,
                            const float* __restrict__ Wk, const float* __restrict__ bk) {
    int idx = blockIdx.x * 256 + threadIdx.x;
    if (idx < CCH * 128) {
        int c = idx >> 7, j = idx & 127;
        float v = 0.f;
        if (j < 72)      v = Ww[c * 72 + j];
        else if (j < 81) v = Wk[c * 9 + (j - 72)];
        g_Wpad[idx] = v;
    }
    if (idx < 128)
        g_bpad[idx] = (idx < 72) ? bw[idx] : ((idx < 81) ? bk[idx - 72] : 0.f);
}

// ---------------- K2b: weight images (gamma folded, tf32/fp16) --------------
__global__ __launch_bounds__(256) void prep2_kernel(const float* __restrict__ Wv,
                                                    const float* __restrict__ g2,
                                                    const float* __restrict__ Wo,
                                                    const float* __restrict__ g1) {
    const int e = blockIdx.x * 256 + threadIdx.x;      // 0..65535
    { const int c = e >> 8;
      g_W2v[e] = __uint_as_float(f2tf32(g2[c] * Wv[e])); }
    { const int j = e >> 8, c = e & 255;
      g_WoT[e] = __float2half(Wo[c * 256 + j]); }
    if (e < CCH * 128) {
        const int c = e >> 7;
        g_W2w[e] = __uint_as_float(f2tf32(g1[c] * g_Wpad[e]));
    }
}

// ---------------- K2c: epilogue vectors u, v ---------------------------------
__global__ __launch_bounds__(256) void prep3_kernel(const float* __restrict__ Wv,
                                                    const float* __restrict__ bv,
                                                    const float* __restrict__ g2,
                                                    const float* __restrict__ b2,
                                                    const float* __restrict__ g1,
                                                    const float* __restrict__ b1) {
    const int t = threadIdx.x;
    if (blockIdx.x == 0) {
        float u = 0.f, v = 0.f;
        for (int c = 0; c < CCH; ++c) {
            const float w = Wv[c * 256 + t];
            u = fmaf(g2[c], w, u);
            v = fmaf(b2[c], w, v);
        }
        g_uv[t] = u; g_vv[t] = v + bv[t];
    } else if (t < 128) {
        float u = 0.f, v = 0.f;
        for (int c = 0; c < CCH; ++c) {
            const float w = g_Wpad[c * 128 + t];
            u = fmaf(g1[c], w, u);
            v = fmaf(b1[c], w, v);
        }
        g_uw[t] = u; g_vw[t] = v + g_bpad[t];
    }
}

// ---------------- K3: tf32 GEMM, cp.async 3-stage pipeline ------------------
// MODE 0: g_value[m, j0+j] = rstd*(x2 @ W2v) - rstd*mean*u + v   (fp16 out)
// MODE 1: g_logits[m, j]   = rstd*(x1 @ W2w) - rstd*mean*u + v   (fp32 out)
// Weight/epilogue tables are selected INSIDE the kernel (device symbols are
// not valid as host-side kernel arguments).
template <int MODE>
__global__ __launch_bounds__(256, 2) void gemm_tf32(const float* __restrict__ feats) {
    extern __shared__ char smem_raw[];
    const int STG = 32 * PADM;                       // floats per stage matrix
    float* Asf = reinterpret_cast<float*>(smem_raw); // 3 stages
    float* Bsf = Asf + 3 * STG;
    float* mean_s = Bsf + 3 * STG;
    float* rstd_s = mean_s + 128;
    float* u_s = rstd_s + 128;
    float* v_s = u_s + 128;

    const float* W2   = (MODE == 0) ? g_W2v : g_W2w;
    const float* uvec = (MODE == 0) ? g_uv : g_uw;
    const float* vvec = (MODE == 0) ? g_vv : g_vw;

    const int t = threadIdx.x, lane = t & 31, wid = t >> 5;
    const int lk = lane & 3, lr = lane >> 2;
    const int mb = (wid & 1) * 64, nb = (wid >> 1) * 32;

    const int m0 = blockIdx.x * 128, j0 = blockIdx.y * 128;
    const int b = m0 >> 15, n0 = m0 & (HW - 1);
    const int which = (MODE == 0) ? 1 : 0;
    const int LDB = (MODE == 0) ? 256 : 128;

    if (t < 128) {
        mean_s[t] = g_mean[which * NPIX + m0 + t];
        rstd_s[t] = g_rstd[which * NPIX + m0 + t];
        u_s[t] = uvec[j0 + t];
        v_s[t] = vvec[j0 + t];
    }

    const float* fb = feats + ((size_t)b << 23) + n0;
    const uint32_t sbA = smem_u32(Asf);
    const uint32_t sbB = smem_u32(Bsf);
    const int fc0 = t >> 5;              // 0..7
    const int fm4 = (t & 31) << 2;       // 0..124

    auto fill = [&](int s, int kt) {
        const int k0 = kt * 32;
        const uint32_t aoff = sbA + (uint32_t)s * STG * 4;
        const uint32_t boff = sbB + (uint32_t)s * STG * 4;
#pragma unroll
        for (int i = 0; i < 4; ++i) {
            const int c = fc0 + i * 8;
            CP16(aoff + (uint32_t)(c * PADM + fm4) * 4,
                 fb + ((size_t)(k0 + c) << 15) + fm4);
            CP16(boff + (uint32_t)(c * PADM + fm4) * 4,
                 W2 + (size_t)(k0 + c) * LDB + j0 + fm4);
        }
    };

    float acc[4][4][4];
#pragma unroll
    for (int mi = 0; mi < 4; ++mi)
#pragma unroll
        for (int ni = 0; ni < 4; ++ni)
#pragma unroll
            for (int q = 0; q < 4; ++q) acc[mi][ni][q] = 0.f;

    fill(0, 0); CPCOMMIT();
    fill(1, 1); CPCOMMIT();

    for (int kt = 0; kt < 8; ++kt) {
        CPWAIT1();
        __syncthreads();
        if (kt + 2 < 8) fill((kt + 2) % 3, kt + 2);
        CPCOMMIT();

        const uint32_t* As = reinterpret_cast<const uint32_t*>(Asf + (kt % 3) * STG);
        const uint32_t* Bs = reinterpret_cast<const uint32_t*>(Bsf + (kt % 3) * STG);
#pragma unroll
        for (int ks = 0; ks < 4; ++ks) {
            const int kb = ks * 8;
            uint32_t a[4][4];
#pragma unroll
            for (int mi = 0; mi < 4; ++mi) {
                const uint32_t* Ab = &As[(kb + lk) * PADM + mb + 16 * mi + lr];
                a[mi][0] = Ab[0];
                a[mi][1] = Ab[8];
                a[mi][2] = Ab[4 * PADM];
                a[mi][3] = Ab[4 * PADM + 8];
            }
            uint32_t bf[4][2];
#pragma unroll
            for (int ni = 0; ni < 4; ++ni) {
                const uint32_t* Bb = &Bs[(kb + lk) * PADM + nb + 8 * ni + lr];
                bf[ni][0] = Bb[0];
                bf[ni][1] = Bb[4 * PADM];
            }
#pragma unroll
            for (int mi = 0; mi < 4; ++mi)
#pragma unroll
                for (int ni = 0; ni < 4; ++ni) {
                    asm volatile(
                        "mma.sync.aligned.m16n8k8.row.col.f32.tf32.tf32.f32 "
                        "{%0,%1,%2,%3}, {%4,%5,%6,%7}, {%8,%9}, {%0,%1,%2,%3};"
                        : "+f"(acc[mi][ni][0]), "+f"(acc[mi][ni][1]),
                          "+f"(acc[mi][ni][2]), "+f"(acc[mi][ni][3])
                        : "r"(a[mi][0]), "r"(a[mi][1]), "r"(a[mi][2]), "r"(a[mi][3]),
                          "r"(bf[ni][0]), "r"(bf[ni][1]));
                }
        }
    }

    // ---- epilogue: C = rstd*D - rstd*mean*u + v ----
#pragma unroll
    for (int mi = 0; mi < 4; ++mi) {
        const int ml = mb + 16 * mi + lr;
        const float r0 = rstd_s[ml],     rm0 = r0 * mean_s[ml];
        const float r1 = rstd_s[ml + 8], rm1 = r1 * mean_s[ml + 8];
#pragma unroll
        for (int ni = 0; ni < 4; ++ni) {
            const int jc = nb + 8 * ni + 2 * lk;
            const float u0 = u_s[jc], u1 = u_s[jc + 1];
            const float v0 = v_s[jc], v1 = v_s[jc + 1];
            const float c00 = fmaf(r0, acc[mi][ni][0], fmaf(-rm0, u0, v0));
            const float c01 = fmaf(r0, acc[mi][ni][1], fmaf(-rm0, u1, v1));
            const float c10 = fmaf(r1, acc[mi][ni][2], fmaf(-rm1, u0, v0));
            const float c11 = fmaf(r1, acc[mi][ni][3], fmaf(-rm1, u1, v1));
            if (MODE == 0) {
                const __half2 h0 = __floats2half2_rn(c00, c01);
                const __half2 h1 = __floats2half2_rn(c10, c11);
                *reinterpret_cast<__half2*>(g_value + (size_t)(m0 + ml) * 256 + j0 + jc) = h0;
                *reinterpret_cast<__half2*>(g_value + (size_t)(m0 + ml + 8) * 256 + j0 + jc) = h1;
            } else {
                float2 r0v; r0v.x = c00; r0v.y = c01;
                float2 r1v; r1v.x = c10; r1v.y = c11;
                *reinterpret_cast<float2*>(g_logits + (size_t)(m0 + ml) * 128 + jc) = r0v;
                *reinterpret_cast<float2*>(g_logits + (size_t)(m0 + ml + 8) * 128 + jc) = r1v;
            }
        }
    }
}

// ---------------- K6: fp16 GEMM (out = Wo^T @ agg^T + bo), cp.async 3-stage -
__global__ __launch_bounds__(256, 2) void gemm_f16(const float* __restrict__ bias,
                                                   float* __restrict__ out) {
    extern __shared__ char smem_raw[];
    const int STGH = 128 * PADK;                        // halves per stage matrix
    __half* Ash = reinterpret_cast<__half*>(smem_raw);  // 3 stages (Wo^T tile)
    __half* Bsh = Ash + 3 * STGH;                       // 3 stages (agg tile)

    const int t = threadIdx.x, lane = t & 31, wid = t >> 5;
    const int lk = lane & 3, lr = lane >> 2;
    const int mb = (wid & 1) * 64, nb = (wid >> 1) * 32;

    const int n0 = blockIdx.x * 128, j0 = blockIdx.y * 128;
    const int b = n0 >> 15, nbase = n0 & (HW - 1);

    const uint32_t sbA = smem_u32(Ash);
    const uint32_t sbB = smem_u32(Bsh);

    auto fill = [&](int s, int kt) {
        const int k0 = kt * 32;
#pragma unroll
        for (int i = 0; i < 2; ++i) {
            const int idx = t + i * 256;
            const int row = idx >> 2, seg = (idx & 3) << 3;   // seg in halves
            CP16(sbA + (uint32_t)s * STGH * 2 + (uint32_t)(row * PADK + seg) * 2,
                 g_WoT + (size_t)(j0 + row) * 256 + k0 + seg);
            CP16(sbB + (uint32_t)s * STGH * 2 + (uint32_t)(row * PADK + seg) * 2,
                 g_agg + ((size_t)(n0 + row) << 8) + k0 + seg);
        }
    };

    float acc[4][4][4];
#pragma unroll
    for (int mi = 0; mi < 4; ++mi)
#pragma unroll
        for (int ni = 0; ni < 4; ++ni)
#pragma unroll
            for (int q = 0; q < 4; ++q) acc[mi][ni][q] = 0.f;

    fill(0, 0); CPCOMMIT();
    fill(1, 1); CPCOMMIT();

    for (int kt = 0; kt < 8; ++kt) {
        CPWAIT1();
        __syncthreads();
        if (kt + 2 < 8) fill((kt + 2) % 3, kt + 2);
        CPCOMMIT();

        const __half* At = Ash + (kt % 3) * STGH;
        const __half* Bt = Bsh + (kt % 3) * STGH;
#pragma unroll
        for (int ks = 0; ks < 2; ++ks) {
            const int kk = ks * 16 + lk * 2;
            uint32_t a[4][4];
#pragma unroll
            for (int mi = 0; mi < 4; ++mi) {
                const __half* Ab = At + (mb + 16 * mi + lr) * PADK + kk;
                a[mi][0] = *reinterpret_cast<const uint32_t*>(Ab);
                a[mi][1] = *reinterpret_cast<const uint32_t*>(Ab + 8 * PADK);
                a[mi][2] = *reinterpret_cast<const uint32_t*>(Ab + 8);
                a[mi][3] = *reinterpret_cast<const uint32_t*>(Ab + 8 * PADK + 8);
            }
            uint32_t bf[4][2];
#pragma unroll
            for (int ni = 0; ni < 4; ++ni) {
                const __half* Bb = Bt + (nb + 8 * ni + lr) * PADK + kk;
                bf[ni][0] = *reinterpret_cast<const uint32_t*>(Bb);
                bf[ni][1] = *reinterpret_cast<const uint32_t*>(Bb + 8);
            }
#pragma unroll
            for (int mi = 0; mi < 4; ++mi)
#pragma unroll
                for (int ni = 0; ni < 4; ++ni) {
                    asm volatile(
                        "mma.sync.aligned.m16n8k16.row.col.f32.f16.f16.f32 "
                        "{%0,%1,%2,%3}, {%4,%5,%6,%7}, {%8,%9}, {%0,%1,%2,%3};"
                        : "+f"(acc[mi][ni][0]), "+f"(acc[mi][ni][1]),
                          "+f"(acc[mi][ni][2]), "+f"(acc[mi][ni][3])
                        : "r"(a[mi][0]), "r"(a[mi][1]), "r"(a[mi][2]), "r"(a[mi][3]),
                          "r"(bf[ni][0]), "r"(bf[ni][1]));
                }
        }
    }

    // ---- epilogue: out[b][j][n] ----
#pragma unroll
    for (int mi = 0; mi < 4; ++mi) {
        const int j = j0 + mb + 16 * mi + lr;
        const float br0 = __ldg(bias + j);
        const float br1 = __ldg(bias + j + 8);
        float* d0 = out + (((size_t)(b * CCH + j)) << 15) + nbase;
        float* d1 = out + (((size_t)(b * CCH + j + 8)) << 15) + nbase;
#pragma unroll
        for (int ni = 0; ni < 4; ++ni) {
            const int cb = nb + 8 * ni + 2 * lk;
            float2 r0, r1;
            r0.x = acc[mi][ni][0] + br0;
            r0.y = acc[mi][ni][1] + br0;
            r1.x = acc[mi][ni][2] + br1;
            r1.y = acc[mi][ni][3] + br1;
            *reinterpret_cast<float2*>(d0 + cb) = r0;
            *reinterpret_cast<float2*>(d1 + cb) = r1;
        }
    }
}

// ---------------- K5: fused softmax + deformable gather (4 px/block) --------
__global__ __launch_bounds__(256) void agg_kernel(const float* __restrict__ kp) {
    __shared__ float w_s[4][72];
    __shared__ int   sxi[4][PPTS][2];
    __shared__ float sxy[4][PPTS][2];

    const int t = threadIdx.x;
    const int pg0 = blockIdx.x << 2;

    if (t < 32) {
        const int lp = t >> 3, g = t & 7;
        const float* row = g_logits + (size_t)(pg0 + lp) * 128 + g;
        float l[PPTS];
        float mx = -1e30f;
#pragma unroll
        for (int p = 0; p < PPTS; ++p) { l[p] = row[p * 8]; mx = fmaxf(mx, l[p]); }
        float s = 0.f;
#pragma unroll
        for (int p = 0; p < PPTS; ++p) { l[p] = __expf(l[p] - mx); s += l[p]; }
        const float inv = 1.f / s;
#pragma unroll
        for (int p = 0; p < PPTS; ++p) w_s[lp][p * 8 + g] = l[p] * inv;
    }
    if (t >= 64 && t < 64 + 4 * PPTS) {
        const int idx = t - 64;
        const int lp = idx / PPTS, p = idx - lp * PPTS;
        const size_t kidx = ((size_t)(pg0 + lp) * PPTS + p) * 2;
        const float x = kp[kidx] * (float)WWD - 0.5f;
        const float y = kp[kidx + 1] * (float)HH - 0.5f;
        const float xf = floorf(x), yf = floorf(y);
        sxi[lp][p][0] = (int)xf; sxi[lp][p][1] = (int)yf;
        sxy[lp][p][0] = x - xf;  sxy[lp][p][1] = y - yf;
    }
    __syncthreads();

    const int lp = t >> 6, ch = t & 63;
    const int c = ch << 2, g = ch >> 3;
    const int pg = pg0 + lp, b = pg >> 15;
    const __half* vb = g_value + ((size_t)b << 23) + c;

    float ax = 0.f, ay = 0.f, az = 0.f, aw = 0.f;
#pragma unroll
    for (int p = 0; p < PPTS; ++p) {
        const int x0 = sxi[lp][p][0], y0 = sxi[lp][p][1];
        const float wx = sxy[lp][p][0], wy = sxy[lp][p][1];
        const float wp = w_s[lp][p * 8 + g];
        const bool yv0 = (y0 >= 0) & (y0 < HH);
        const bool yv1 = (y0 + 1 >= 0) & (y0 + 1 < HH);
        const bool xv0 = (x0 >= 0) & (x0 < WWD);
        const bool xv1 = (x0 + 1 >= 0) & (x0 + 1 < WWD);
        float2 v00a = {0, 0}, v00b = {0, 0}, v01a = {0, 0}, v01b = {0, 0};
        float2 v10a = {0, 0}, v10b = {0, 0}, v11a = {0, 0}, v11b = {0, 0};
        if (yv0 && xv0) {
            const uint2 raw = *reinterpret_cast<const uint2*>(vb + ((size_t)(y0 * WWD + x0) << 8));
            v00a = __half22float2(*reinterpret_cast<const __half2*>(&raw.x));
            v00b = __half22float2(*reinterpret_cast<const __half2*>(&raw.y));
        }
        if (yv0 && xv1) {
            const uint2 raw = *reinterpret_cast<const uint2*>(vb + ((size_t)(y0 * WWD + x0 + 1) << 8));
            v01a = __half22float2(*reinterpret_cast<const __half2*>(&raw.x));
            v01b = __half22float2(*reinterpret_cast<const __half2*>(&raw.y));
        }
        if (yv1 && xv0) {
            const uint2 raw = *reinterpret_cast<const uint2*>(vb + ((size_t)((y0 + 1) * WWD + x0) << 8));
            v10a = __half22float2(*reinterpret_cast<const __half2*>(&raw.x));
            v10b = __half22float2(*reinterpret_cast<const __half2*>(&raw.y));
        }
        if (yv1 && xv1) {
            const uint2 raw = *reinterpret_cast<const uint2*>(vb + ((size_t)((y0 + 1) * WWD + x0 + 1) << 8));
            v11a = __half22float2(*reinterpret_cast<const __half2*>(&raw.x));
            v11b = __half22float2(*reinterpret_cast<const __half2*>(&raw.y));
        }
        const float w00 = (1.f - wx) * (1.f - wy), w01 = wx * (1.f - wy);
        const float w10 = (1.f - wx) * wy,         w11 = wx * wy;
        ax = fmaf(wp, v00a.x * w00 + v01a.x * w01 + v10a.x * w10 + v11a.x * w11, ax);
        ay = fmaf(wp, v00a.y * w00 + v01a.y * w01 + v10a.y * w10 + v11a.y * w11, ay);
        az = fmaf(wp, v00b.x * w00 + v01b.x * w01 + v10b.x * w10 + v11b.x * w11, az);
        aw = fmaf(wp, v00b.y * w00 + v01b.y * w01 + v10b.y * w10 + v11b.y * w11, aw);
    }
    const __half2 h0 = __floats2half2_rn(ax, ay);
    const __half2 h1 = __floats2half2_rn(az, aw);
    uint2 st;
    st.x = *reinterpret_cast<const uint32_t*>(&h0);
    st.y = *reinterpret_cast<const uint32_t*>(&h1);
    *reinterpret_cast<uint2*>(g_agg + ((size_t)pg << 8) + c) = st;
}

// ---------------- launch -----------------------------------------------------
#define SMEM_T ((6 * 32 * PADM + 512) * 4)     // 106496 B
#define SMEM_H (6 * 128 * PADK * 2)            // 61440 B

extern "C" void kernel_launch(void* const* d_in, const int* in_sizes, int n_in,
                              void* d_out, int out_size) {
    const float* feats1 = (const float*)d_in[0];
    const float* feats2 = (const float*)d_in[1];
    const float* anchor = (const float*)d_in[2];
    const float* n1g = (const float*)d_in[3];
    const float* n1b = (const float*)d_in[4];
    const float* n2g = (const float*)d_in[5];
    const float* n2b = (const float*)d_in[6];
    const float* Wv  = (const float*)d_in[7];
    const float* bv  = (const float*)d_in[8];
    const float* Ww  = (const float*)d_in[9];
    const float* bw  = (const float*)d_in[10];
    const float* Wk  = (const float*)d_in[11];
    const float* bk  = (const float*)d_in[12];
    const float* Wo  = (const float*)d_in[13];
    const float* bo  = (const float*)d_in[14];

    float* out    = (float*)d_out;
    float* kp_out = out + (size_t)16777216;   // B*C*H*W

    cudaFuncSetAttribute(gemm_tf32<0>, cudaFuncAttributeMaxDynamicSharedMemorySize, SMEM_T);
    cudaFuncSetAttribute(gemm_tf32<1>, cudaFuncAttributeMaxDynamicSharedMemorySize, SMEM_T);
    cudaFuncSetAttribute(gemm_f16, cudaFuncAttributeMaxDynamicSharedMemorySize, SMEM_H);

    stats2_kernel<<<NPIX / 512, 128>>>(feats2);
    stats1_kernel<<<NPIX / 256, 128>>>(feats1, n1g, n1b, Wk, bk, anchor, kp_out);
    prep_kernel<<<128, 256>>>(Ww, bw, Wk, bk);
    prep2_kernel<<<256, 256>>>(Wv, n2g, Wo, n1g);
    prep3_kernel<<<2, 256>>>(Wv, bv, n2g, n2b, n1g, n1b);
    gemm_tf32<0><<<dim3(512, 2), 256, SMEM_T>>>(feats2);
    gemm_tf32<1><<<dim3(512, 1), 256, SMEM_T>>>(feats1);
    agg_kernel<<<NPIX / 4, 256>>>(kp_out);
    gemm_f16<<<dim3(512, 2), 256, SMEM_H>>>(bo, out);
}

// round 9
// speedup vs baseline: 2.5276x; 1.1139x over previous
#include <cuda_runtime.h>
#include <cuda_fp16.h>
#include <cstdint>
#include <math.h>

// Problem dims
#define HW   32768
#define CCH  256
#define HH   128
#define WWD  256
#define NPIX 65536      // B * HW
#define PPTS 9
#define GRP  8

#define PADM 136        // tf32 SMEM row stride (floats)
#define PADK 40         // f16 SMEM row stride (halves)

// ---------------- scratch (static device globals; no allocation) ------------
__device__ float  g_mean[NPIX];                   // feats1 stats only
__device__ float  g_rstd[NPIX];
__device__ __half g_value[(size_t)NPIX * CCH];    // (pixel, j) fp16
__device__ float  g_logits[(size_t)NPIX * 128];   // cols 0..71 consumed
__device__ __half g_agg[(size_t)NPIX * CCH];      // fp16
__device__ float  g_W2v[CCH * 256];               // tf32(gamma2*Wv) [c][j]
__device__ float  g_W2w[CCH * 128];               // tf32(gamma1*[Ww|Wk|0]) [c][j]
__device__ __half g_WoT[256 * 256];               // Wo^T fp16 [j][c]
__device__ float  g_uv[256], g_vv[256];           // mode0 epilogue vectors
__device__ float  g_uw[128], g_vw[128];           // mode1 epilogue vectors

__device__ __forceinline__ uint32_t f2tf32(float f) {
    uint32_t r;
    asm("cvt.rna.tf32.f32 %0, %1;" : "=r"(r) : "f"(f));
    return r;
}
__device__ __forceinline__ uint32_t smem_u32(const void* p) {
    uint32_t a;
    asm("{ .reg .u64 t; cvta.to.shared.u64 t, %1; cvt.u32.u64 %0, t; }" : "=r"(a) : "l"(p));
    return a;
}
__device__ __forceinline__ float2 h2f(uint32_t h) {
    return __half22float2(*reinterpret_cast<const __half2*>(&h));
}
#define CP16(dst, src) \
    asm volatile("cp.async.cg.shared.global [%0], [%1], 16;" :: "r"(dst), "l"(src))
#define CPCOMMIT() asm volatile("cp.async.commit_group;" ::)
#define CPWAIT1()  asm volatile("cp.async.wait_group 1;" ::)

__device__ __forceinline__ float wpad_val(const float* __restrict__ Ww,
                                          const float* __restrict__ Wk,
                                          int c, int j) {
    if (j < 72) return Ww[c * 72 + j];
    if (j < 81) return Wk[c * 9 + (j - 72)];
    return 0.f;
}

// ---------------- K1: feats1 LN stats + fp32 keypoint offsets (2 px/thread) -
__global__ __launch_bounds__(128) void stats1_kernel(const float* __restrict__ f1,
                                                     const float* __restrict__ gamma,
                                                     const float* __restrict__ beta,
                                                     const float* __restrict__ Wk,
                                                     const float* __restrict__ bk,
                                                     const float* __restrict__ anchor,
                                                     float* __restrict__ kp_out) {
    __shared__ float wk_s[CCH * PPTS];
    __shared__ float cA[PPTS], cB[PPTS], bk_s[PPTS];
    const int t = threadIdx.x;

    for (int idx = t; idx < CCH * PPTS; idx += 128) {
        const int c = idx / PPTS;
        wk_s[idx] = gamma[c] * Wk[idx];
    }
    if (t < PPTS) {
        float a = 0.f, bs = 0.f;
        for (int c = 0; c < CCH; ++c) {
            a  += beta[c]  * Wk[c * PPTS + t];
            bs += gamma[c] * Wk[c * PPTS + t];
        }
        cA[t] = a; cB[t] = bs; bk_s[t] = bk[t];
    }
    __syncthreads();

    const int pg0 = (blockIdx.x * 128 + t) * 2;
    const int b = pg0 >> 15;
    const int n = pg0 & (HW - 1);
    const float* base = f1 + ((size_t)b << 23) + n;

    float2 s = {0, 0}, s2 = {0, 0};
    float o0[PPTS], o1[PPTS];
#pragma unroll
    for (int p = 0; p < PPTS; ++p) { o0[p] = 0.f; o1[p] = 0.f; }

    for (int c = 0; c < CCH; ++c) {
        const float2 v = *reinterpret_cast<const float2*>(base + ((size_t)c << 15));
        s.x += v.x; s.y += v.y;
        s2.x += v.x * v.x; s2.y += v.y * v.y;
#pragma unroll
        for (int p = 0; p < PPTS; ++p) {
            const float w = wk_s[c * PPTS + p];
            o0[p] = fmaf(v.x, w, o0[p]);
            o1[p] = fmaf(v.y, w, o1[p]);
        }
    }
    const float inv = 1.f / 256.f;
#pragma unroll
    for (int i = 0; i < 2; ++i) {
        const int pg = pg0 + i;
        const float m = (i ? s.y : s.x) * inv;
        const float q = (i ? s2.y : s2.x) * inv;
        const float r = rsqrtf(q - m * m + 1e-5f);
        g_mean[pg] = m;
        g_rstd[pg] = r;
        const float ax = anchor[2 * pg], ay = anchor[2 * pg + 1];
        const float* oo = i ? o1 : o0;
#pragma unroll
        for (int p = 0; p < PPTS; ++p) {
            const float off = r * (oo[p] - m * cB[p]) + cA[p] + bk_s[p];
            kp_out[((size_t)pg * PPTS + p) * 2]     = ax + off;
            kp_out[((size_t)pg * PPTS + p) * 2 + 1] = ay;
        }
    }
}

// ---------------- K2: single fused prep (weight images + epilogue vectors) --
__global__ __launch_bounds__(256) void prep_all(const float* __restrict__ Wv,
                                                const float* __restrict__ g2,
                                                const float* __restrict__ b2,
                                                const float* __restrict__ bv,
                                                const float* __restrict__ Wo,
                                                const float* __restrict__ g1,
                                                const float* __restrict__ b1,
                                                const float* __restrict__ Ww,
                                                const float* __restrict__ bw,
                                                const float* __restrict__ Wk,
                                                const float* __restrict__ bk) {
    const int bx = blockIdx.x, t = threadIdx.x;
    if (bx < 256) {
        const int e = bx * 256 + t;
        { const int c = e >> 8;
          g_W2v[e] = __uint_as_float(f2tf32(g2[c] * Wv[e])); }
        { const int j = e >> 8, c = e & 255;
          g_WoT[e] = __float2half(Wo[c * 256 + j]); }
        if (e < CCH * 128) {
            const int c = e >> 7, j = e & 127;
            g_W2w[e] = __uint_as_float(f2tf32(g1[c] * wpad_val(Ww, Wk, c, j)));
        }
    } else if (bx == 256) {
        float u = 0.f, v = 0.f;
        for (int c = 0; c < CCH; ++c) {
            const float w = Wv[c * 256 + t];
            u = fmaf(g2[c], w, u);
            v = fmaf(b2[c], w, v);
        }
        g_uv[t] = u; g_vv[t] = v + bv[t];
    } else if (t < 128) {
        float u = 0.f, v = 0.f;
        for (int c = 0; c < CCH; ++c) {
            const float w = wpad_val(Ww, Wk, c, t);
            u = fmaf(g1[c], w, u);
            v = fmaf(b1[c], w, v);
        }
        const float bp = (t < 72) ? bw[t] : ((t < 81) ? bk[t - 72] : 0.f);
        g_uw[t] = u; g_vw[t] = v + bp;
    }
}

// ---------------- K3: tf32 GEMM, cp.async 3-stage pipeline ------------------
// MODE 0: g_value[m, j0+j] = rstd*(x2 @ W2v) - rstd*mean*u + v   (fp16 out)
//         feats2 LN stats computed IN-KERNEL from the staged A tiles.
// MODE 1: g_logits[m, j]   = rstd*(x1 @ W2w) - rstd*mean*u + v   (fp32 out)
template <int MODE>
__global__ __launch_bounds__(256, 2) void gemm_tf32(const float* __restrict__ feats) {
    extern __shared__ char smem_raw[];
    const int STG = 32 * PADM;                       // floats per stage matrix
    float* Asf = reinterpret_cast<float*>(smem_raw); // 3 stages
    float* Bsf = Asf + 3 * STG;
    float* mean_s = Bsf + 3 * STG;
    float* rstd_s = mean_s + 128;
    float* u_s = rstd_s + 128;
    float* v_s = u_s + 128;
    float* red1 = v_s + 128;    // 256
    float* red2 = red1 + 256;   // 256

    const float* W2   = (MODE == 0) ? g_W2v : g_W2w;
    const float* uvec = (MODE == 0) ? g_uv : g_uw;
    const float* vvec = (MODE == 0) ? g_vv : g_vw;

    const int t = threadIdx.x, lane = t & 31, wid = t >> 5;
    const int lk = lane & 3, lr = lane >> 2;
    const int mb = (wid & 1) * 64, nb = (wid >> 1) * 32;

    const int m0 = blockIdx.x * 128, j0 = blockIdx.y * 128;
    const int b = m0 >> 15, n0 = m0 & (HW - 1);
    const int LDB = (MODE == 0) ? 256 : 128;

    if (t < 128) {
        u_s[t] = uvec[j0 + t];
        v_s[t] = vvec[j0 + t];
        if (MODE == 1) {
            mean_s[t] = g_mean[m0 + t];
            rstd_s[t] = g_rstd[m0 + t];
        }
    }

    const float* fb = feats + ((size_t)b << 23) + n0;
    const uint32_t sbA = smem_u32(Asf);
    const uint32_t sbB = smem_u32(Bsf);
    const int fc0 = t >> 5;              // 0..7
    const int fm4 = (t & 31) << 2;       // 0..124

    auto fill = [&](int s, int kt) {
        const int k0 = kt * 32;
        const uint32_t aoff = sbA + (uint32_t)s * STG * 4;
        const uint32_t boff = sbB + (uint32_t)s * STG * 4;
#pragma unroll
        for (int i = 0; i < 4; ++i) {
            const int c = fc0 + i * 8;
            CP16(aoff + (uint32_t)(c * PADM + fm4) * 4,
                 fb + ((size_t)(k0 + c) << 15) + fm4);
            CP16(boff + (uint32_t)(c * PADM + fm4) * 4,
                 W2 + (size_t)(k0 + c) * LDB + j0 + fm4);
        }
    };

    float acc[4][4][4];
#pragma unroll
    for (int mi = 0; mi < 4; ++mi)
#pragma unroll
        for (int ni = 0; ni < 4; ++ni)
#pragma unroll
            for (int q = 0; q < 4; ++q) acc[mi][ni][q] = 0.f;

    // in-kernel stats accumulators (MODE 0)
    float s1 = 0.f, s2acc = 0.f;
    const int sm = t & 127, sh = (t >> 7) << 4;   // row, k-half offset

    fill(0, 0); CPCOMMIT();
    fill(1, 1); CPCOMMIT();

    for (int kt = 0; kt < 8; ++kt) {
        CPWAIT1();
        __syncthreads();
        if (kt + 2 < 8) fill((kt + 2) % 3, kt + 2);
        CPCOMMIT();

        const float* Ast = Asf + (kt % 3) * STG;
        if (MODE == 0) {
#pragma unroll
            for (int cc = 0; cc < 16; ++cc) {
                const float v = Ast[(sh + cc) * PADM + sm];
                s1 += v; s2acc = fmaf(v, v, s2acc);
            }
        }

        const uint32_t* As = reinterpret_cast<const uint32_t*>(Ast);
        const uint32_t* Bs = reinterpret_cast<const uint32_t*>(Bsf + (kt % 3) * STG);
#pragma unroll
        for (int ks = 0; ks < 4; ++ks) {
            const int kb = ks * 8;
            uint32_t a[4][4];
#pragma unroll
            for (int mi = 0; mi < 4; ++mi) {
                const uint32_t* Ab = &As[(kb + lk) * PADM + mb + 16 * mi + lr];
                a[mi][0] = Ab[0];
                a[mi][1] = Ab[8];
                a[mi][2] = Ab[4 * PADM];
                a[mi][3] = Ab[4 * PADM + 8];
            }
            uint32_t bf[4][2];
#pragma unroll
            for (int ni = 0; ni < 4; ++ni) {
                const uint32_t* Bb = &Bs[(kb + lk) * PADM + nb + 8 * ni + lr];
                bf[ni][0] = Bb[0];
                bf[ni][1] = Bb[4 * PADM];
            }
#pragma unroll
            for (int mi = 0; mi < 4; ++mi)
#pragma unroll
                for (int ni = 0; ni < 4; ++ni) {
                    asm volatile(
                        "mma.sync.aligned.m16n8k8.row.col.f32.tf32.tf32.f32 "
                        "{%0,%1,%2,%3}, {%4,%5,%6,%7}, {%8,%9}, {%0,%1,%2,%3};"
                        : "+f"(acc[mi][ni][0]), "+f"(acc[mi][ni][1]),
                          "+f"(acc[mi][ni][2]), "+f"(acc[mi][ni][3])
                        : "r"(a[mi][0]), "r"(a[mi][1]), "r"(a[mi][2]), "r"(a[mi][3]),
                          "r"(bf[ni][0]), "r"(bf[ni][1]));
                }
        }
    }

    if (MODE == 0) {
        red1[t] = s1; red2[t] = s2acc;
        __syncthreads();
        if (t < 128) {
            const float S1 = red1[t] + red1[t + 128];
            const float S2 = red2[t] + red2[t + 128];
            const float m = S1 * (1.f / 256.f);
            mean_s[t] = m;
            rstd_s[t] = rsqrtf(S2 * (1.f / 256.f) - m * m + 1e-5f);
        }
        __syncthreads();
    }

    // ---- epilogue: C = rstd*D - rstd*mean*u + v ----
#pragma unroll
    for (int mi = 0; mi < 4; ++mi) {
        const int ml = mb + 16 * mi + lr;
        const float r0 = rstd_s[ml],     rm0 = r0 * mean_s[ml];
        const float r1 = rstd_s[ml + 8], rm1 = r1 * mean_s[ml + 8];
#pragma unroll
        for (int ni = 0; ni < 4; ++ni) {
            const int jc = nb + 8 * ni + 2 * lk;
            const float u0 = u_s[jc], u1 = u_s[jc + 1];
            const float v0 = v_s[jc], v1 = v_s[jc + 1];
            const float c00 = fmaf(r0, acc[mi][ni][0], fmaf(-rm0, u0, v0));
            const float c01 = fmaf(r0, acc[mi][ni][1], fmaf(-rm0, u1, v1));
            const float c10 = fmaf(r1, acc[mi][ni][2], fmaf(-rm1, u0, v0));
            const float c11 = fmaf(r1, acc[mi][ni][3], fmaf(-rm1, u1, v1));
            if (MODE == 0) {
                const __half2 h0 = __floats2half2_rn(c00, c01);
                const __half2 h1 = __floats2half2_rn(c10, c11);
                *reinterpret_cast<__half2*>(g_value + (size_t)(m0 + ml) * 256 + j0 + jc) = h0;
                *reinterpret_cast<__half2*>(g_value + (size_t)(m0 + ml + 8) * 256 + j0 + jc) = h1;
            } else if (jc < 72) {
                float2 r0v; r0v.x = c00; r0v.y = c01;
                float2 r1v; r1v.x = c10; r1v.y = c11;
                *reinterpret_cast<float2*>(g_logits + (size_t)(m0 + ml) * 128 + jc) = r0v;
                *reinterpret_cast<float2*>(g_logits + (size_t)(m0 + ml + 8) * 128 + jc) = r1v;
            }
        }
    }
}

// ---------------- K6: fp16 GEMM (out = Wo^T @ agg^T + bo), cp.async 3-stage -
__global__ __launch_bounds__(256, 2) void gemm_f16(const float* __restrict__ bias,
                                                   float* __restrict__ out) {
    extern __shared__ char smem_raw[];
    const int STGH = 128 * PADK;                        // halves per stage matrix
    __half* Ash = reinterpret_cast<__half*>(smem_raw);  // 3 stages (Wo^T tile)
    __half* Bsh = Ash + 3 * STGH;                       // 3 stages (agg tile)

    const int t = threadIdx.x, lane = t & 31, wid = t >> 5;
    const int lk = lane & 3, lr = lane >> 2;
    const int mb = (wid & 1) * 64, nb = (wid >> 1) * 32;

    const int n0 = blockIdx.x * 128, j0 = blockIdx.y * 128;
    const int b = n0 >> 15, nbase = n0 & (HW - 1);

    const uint32_t sbA = smem_u32(Ash);
    const uint32_t sbB = smem_u32(Bsh);

    auto fill = [&](int s, int kt) {
        const int k0 = kt * 32;
#pragma unroll
        for (int i = 0; i < 2; ++i) {
            const int idx = t + i * 256;
            const int row = idx >> 2, seg = (idx & 3) << 3;   // seg in halves
            CP16(sbA + (uint32_t)s * STGH * 2 + (uint32_t)(row * PADK + seg) * 2,
                 g_WoT + (size_t)(j0 + row) * 256 + k0 + seg);
            CP16(sbB + (uint32_t)s * STGH * 2 + (uint32_t)(row * PADK + seg) * 2,
                 g_agg + ((size_t)(n0 + row) << 8) + k0 + seg);
        }
    };

    float acc[4][4][4];
#pragma unroll
    for (int mi = 0; mi < 4; ++mi)
#pragma unroll
        for (int ni = 0; ni < 4; ++ni)
#pragma unroll
            for (int q = 0; q < 4; ++q) acc[mi][ni][q] = 0.f;

    fill(0, 0); CPCOMMIT();
    fill(1, 1); CPCOMMIT();

    for (int kt = 0; kt < 8; ++kt) {
        CPWAIT1();
        __syncthreads();
        if (kt + 2 < 8) fill((kt + 2) % 3, kt + 2);
        CPCOMMIT();

        const __half* At = Ash + (kt % 3) * STGH;
        const __half* Bt = Bsh + (kt % 3) * STGH;
#pragma unroll
        for (int ks = 0; ks < 2; ++ks) {
            const int kk = ks * 16 + lk * 2;
            uint32_t a[4][4];
#pragma unroll
            for (int mi = 0; mi < 4; ++mi) {
                const __half* Ab = At + (mb + 16 * mi + lr) * PADK + kk;
                a[mi][0] = *reinterpret_cast<const uint32_t*>(Ab);
                a[mi][1] = *reinterpret_cast<const uint32_t*>(Ab + 8 * PADK);
                a[mi][2] = *reinterpret_cast<const uint32_t*>(Ab + 8);
                a[mi][3] = *reinterpret_cast<const uint32_t*>(Ab + 8 * PADK + 8);
            }
            uint32_t bf[4][2];
#pragma unroll
            for (int ni = 0; ni < 4; ++ni) {
                const __half* Bb = Bt + (nb + 8 * ni + lr) * PADK + kk;
                bf[ni][0] = *reinterpret_cast<const uint32_t*>(Bb);
                bf[ni][1] = *reinterpret_cast<const uint32_t*>(Bb + 8);
            }
#pragma unroll
            for (int mi = 0; mi < 4; ++mi)
#pragma unroll
                for (int ni = 0; ni < 4; ++ni) {
                    asm volatile(
                        "mma.sync.aligned.m16n8k16.row.col.f32.f16.f16.f32 "
                        "{%0,%1,%2,%3}, {%4,%5,%6,%7}, {%8,%9}, {%0,%1,%2,%3};"
                        : "+f"(acc[mi][ni][0]), "+f"(acc[mi][ni][1]),
                          "+f"(acc[mi][ni][2]), "+f"(acc[mi][ni][3])
                        : "r"(a[mi][0]), "r"(a[mi][1]), "r"(a[mi][2]), "r"(a[mi][3]),
                          "r"(bf[ni][0]), "r"(bf[ni][1]));
                }
        }
    }

    // ---- epilogue: out[b][j][n] ----
#pragma unroll
    for (int mi = 0; mi < 4; ++mi) {
        const int j = j0 + mb + 16 * mi + lr;
        const float br0 = __ldg(bias + j);
        const float br1 = __ldg(bias + j + 8);
        float* d0 = out + (((size_t)(b * CCH + j)) << 15) + nbase;
        float* d1 = out + (((size_t)(b * CCH + j + 8)) << 15) + nbase;
#pragma unroll
        for (int ni = 0; ni < 4; ++ni) {
            const int cb = nb + 8 * ni + 2 * lk;
            float2 r0, r1;
            r0.x = acc[mi][ni][0] + br0;
            r0.y = acc[mi][ni][1] + br0;
            r1.x = acc[mi][ni][2] + br1;
            r1.y = acc[mi][ni][3] + br1;
            *reinterpret_cast<float2*>(d0 + cb) = r0;
            *reinterpret_cast<float2*>(d1 + cb) = r1;
        }
    }
}

// ---------------- K5: fused softmax + deformable gather (8 px/block) --------
__global__ __launch_bounds__(256) void agg_kernel(const float* __restrict__ kp) {
    __shared__ float w_s[8][72];
    __shared__ int   sxi[8][PPTS][2];
    __shared__ float sxy[8][PPTS][2];

    const int t = threadIdx.x;
    const int pg0 = blockIdx.x << 3;

    if (t < 64) {
        const int lp = t >> 3, g = t & 7;
        const float* row = g_logits + (size_t)(pg0 + lp) * 128 + g;
        float l[PPTS];
        float mx = -1e30f;
#pragma unroll
        for (int p = 0; p < PPTS; ++p) { l[p] = row[p * 8]; mx = fmaxf(mx, l[p]); }
        float s = 0.f;
#pragma unroll
        for (int p = 0; p < PPTS; ++p) { l[p] = __expf(l[p] - mx); s += l[p]; }
        const float inv = 1.f / s;
#pragma unroll
        for (int p = 0; p < PPTS; ++p) w_s[lp][p * 8 + g] = l[p] * inv;
    }
    if (t >= 128 && t < 128 + 8 * PPTS) {
        const int idx = t - 128;
        const int lp = idx / PPTS, p = idx - lp * PPTS;
        const size_t kidx = ((size_t)(pg0 + lp) * PPTS + p) * 2;
        const float x = kp[kidx] * (float)WWD - 0.5f;
        const float y = kp[kidx + 1] * (float)HH - 0.5f;
        const float xf = floorf(x), yf = floorf(y);
        sxi[lp][p][0] = (int)xf; sxi[lp][p][1] = (int)yf;
        sxy[lp][p][0] = x - xf;  sxy[lp][p][1] = y - yf;
    }
    __syncthreads();

    const int lp = t >> 5, lane = t & 31;
    const int c = lane << 3;          // 8 channels / thread
    const int g = lane >> 2;
    const int pg = pg0 + lp, b = pg >> 15;
    const __half* vb = g_value + ((size_t)b << 23) + c;

    float acc[8];
#pragma unroll
    for (int q = 0; q < 8; ++q) acc[q] = 0.f;

#pragma unroll
    for (int p = 0; p < PPTS; ++p) {
        const int x0 = sxi[lp][p][0], y0 = sxi[lp][p][1];
        const float wx = sxy[lp][p][0], wy = sxy[lp][p][1];
        const float wp = w_s[lp][p * 8 + g];
        const bool yv0 = (y0 >= 0) & (y0 < HH);
        const bool yv1 = (y0 + 1 >= 0) & (y0 + 1 < HH);
        const bool xv0 = (x0 >= 0) & (x0 < WWD);
        const bool xv1 = (x0 + 1 >= 0) & (x0 + 1 < WWD);
        uint4 r00 = {0,0,0,0}, r01 = {0,0,0,0}, r10 = {0,0,0,0}, r11 = {0,0,0,0};
        if (yv0 && xv0) r00 = *reinterpret_cast<const uint4*>(vb + ((size_t)(y0 * WWD + x0) << 8));
        if (yv0 && xv1) r01 = *reinterpret_cast<const uint4*>(vb + ((size_t)(y0 * WWD + x0 + 1) << 8));
        if (yv1 && xv0) r10 = *reinterpret_cast<const uint4*>(vb + ((size_t)((y0 + 1) * WWD + x0) << 8));
        if (yv1 && xv1) r11 = *reinterpret_cast<const uint4*>(vb + ((size_t)((y0 + 1) * WWD + x0 + 1) << 8));
        const float ww00 = wp * (1.f - wx) * (1.f - wy);
        const float ww01 = wp * wx * (1.f - wy);
        const float ww10 = wp * (1.f - wx) * wy;
        const float ww11 = wp * wx * wy;
        const uint32_t* q00 = reinterpret_cast<const uint32_t*>(&r00);
        const uint32_t* q01 = reinterpret_cast<const uint32_t*>(&r01);
        const uint32_t* q10 = reinterpret_cast<const uint32_t*>(&r10);
        const uint32_t* q11 = reinterpret_cast<const uint32_t*>(&r11);
#pragma unroll
        for (int q = 0; q < 4; ++q) {
            const float2 f00 = h2f(q00[q]), f01 = h2f(q01[q]);
            const float2 f10 = h2f(q10[q]), f11 = h2f(q11[q]);
            acc[2*q]   = fmaf(ww00, f00.x, fmaf(ww01, f01.x,
                          fmaf(ww10, f10.x, fmaf(ww11, f11.x, acc[2*q]))));
            acc[2*q+1] = fmaf(ww00, f00.y, fmaf(ww01, f01.y,
                          fmaf(ww10, f10.y, fmaf(ww11, f11.y, acc[2*q+1]))));
        }
    }
    uint4 st;
    uint32_t* sp = reinterpret_cast<uint32_t*>(&st);
#pragma unroll
    for (int q = 0; q < 4; ++q) {
        const __half2 h = __floats2half2_rn(acc[2*q], acc[2*q+1]);
        sp[q] = *reinterpret_cast<const uint32_t*>(&h);
    }
    *reinterpret_cast<uint4*>(g_agg + ((size_t)pg << 8) + c) = st;
}

// ---------------- launch -----------------------------------------------------
#define SMEM_T ((6 * 32 * PADM + 1024) * 4)    // 108544 B (stages + vecs + red)
#define SMEM_H (6 * 128 * PADK * 2)            // 61440 B

extern "C" void kernel_launch(void* const* d_in, const int* in_sizes, int n_in,
                              void* d_out, int out_size) {
    const float* feats1 = (const float*)d_in[0];
    const float* feats2 = (const float*)d_in[1];
    const float* anchor = (const float*)d_in[2];
    const float* n1g = (const float*)d_in[3];
    const float* n1b = (const float*)d_in[4];
    const float* n2g = (const float*)d_in[5];
    const float* n2b = (const float*)d_in[6];
    const float* Wv  = (const float*)d_in[7];
    const float* bv  = (const float*)d_in[8];
    const float* Ww  = (const float*)d_in[9];
    const float* bw  = (const float*)d_in[10];
    const float* Wk  = (const float*)d_in[11];
    const float* bk  = (const float*)d_in[12];
    const float* Wo  = (const float*)d_in[13];
    const float* bo  = (const float*)d_in[14];

    float* out    = (float*)d_out;
    float* kp_out = out + (size_t)16777216;   // B*C*H*W

    cudaFuncSetAttribute(gemm_tf32<0>, cudaFuncAttributeMaxDynamicSharedMemorySize, SMEM_T);
    cudaFuncSetAttribute(gemm_tf32<1>, cudaFuncAttributeMaxDynamicSharedMemorySize, SMEM_T);
    cudaFuncSetAttribute(gemm_f16, cudaFuncAttributeMaxDynamicSharedMemorySize, SMEM_H);

    prep_all<<<258, 256>>>(Wv, n2g, n2b, bv, Wo, n1g, n1b, Ww, bw, Wk, bk);
    stats1_kernel<<<NPIX / 256, 128>>>(feats1, n1g, n1b, Wk, bk, anchor, kp_out);
    gemm_tf32<0><<<dim3(512, 2), 256, SMEM_T>>>(feats2);
    gemm_tf32<1><<<dim3(512, 1), 256, SMEM_T>>>(feats1);
    agg_kernel<<<NPIX / 8, 256>>>(kp_out);
    gemm_f16<<<dim3(512, 2), 256, SMEM_H>>>(bo, out);
}

// round 10
// speedup vs baseline: 3.2094x; 1.2697x over previous
#include <cuda_runtime.h>
#include <cuda_fp16.h>
#include <cstdint>
#include <math.h>

// Problem dims
#define HW   32768
#define CCH  256
#define HH   128
#define WWD  256
#define NPIX 65536      // B * HW
#define PPTS 9
#define GRP  8

#define PADM 136        // tf32 SMEM row stride (floats)
#define PADK 40         // f16 SMEM row stride (halves)

// ---------------- scratch (static device globals; no allocation) ------------
__device__ __half g_value[(size_t)NPIX * CCH];    // (pixel, j) fp16
__device__ float  g_logits[(size_t)NPIX * 128];   // cols 0..71 consumed
__device__ __half g_agg[(size_t)NPIX * CCH];      // fp16
__device__ float  g_W2v[CCH * 256];               // tf32(gamma2*Wv) [c][j]
__device__ float  g_W2w[CCH * 128];               // tf32(gamma1*[Ww|Wk|0]) [c][j]
__device__ __half g_WoT[256 * 256];               // Wo^T fp16 [j][c]
__device__ float  g_uv[256], g_vv[256];           // mode0 epilogue vectors
__device__ float  g_uw[128], g_vw[128];           // mode1 epilogue vectors
__device__ float  g_cA[16], g_cB[16];             // offset epilogue constants

__device__ __forceinline__ uint32_t f2tf32(float f) {
    uint32_t r;
    asm("cvt.rna.tf32.f32 %0, %1;" : "=r"(r) : "f"(f));
    return r;
}
__device__ __forceinline__ uint32_t smem_u32(const void* p) {
    uint32_t a;
    asm("{ .reg .u64 t; cvta.to.shared.u64 t, %1; cvt.u32.u64 %0, t; }" : "=r"(a) : "l"(p));
    return a;
}
__device__ __forceinline__ float2 h2f(uint32_t h) {
    return __half22float2(*reinterpret_cast<const __half2*>(&h));
}
#define CP16(dst, src) \
    asm volatile("cp.async.cg.shared.global [%0], [%1], 16;" :: "r"(dst), "l"(src))
#define CPCOMMIT() asm volatile("cp.async.commit_group;" ::)
#define CPWAIT1()  asm volatile("cp.async.wait_group 1;" ::)

__device__ __forceinline__ float wpad_val(const float* __restrict__ Ww,
                                          const float* __restrict__ Wk,
                                          int c, int j) {
    if (j < 72) return Ww[c * 72 + j];
    if (j < 81) return Wk[c * 9 + (j - 72)];
    return 0.f;
}

// ---------------- K2: single fused prep (weight images + epilogue vectors) --
__global__ __launch_bounds__(256) void prep_all(const float* __restrict__ Wv,
                                                const float* __restrict__ g2,
                                                const float* __restrict__ b2,
                                                const float* __restrict__ bv,
                                                const float* __restrict__ Wo,
                                                const float* __restrict__ g1,
                                                const float* __restrict__ b1,
                                                const float* __restrict__ Ww,
                                                const float* __restrict__ bw,
                                                const float* __restrict__ Wk,
                                                const float* __restrict__ bk) {
    const int bx = blockIdx.x, t = threadIdx.x;
    if (bx < 256) {
        const int e = bx * 256 + t;
        { const int c = e >> 8;
          g_W2v[e] = __uint_as_float(f2tf32(g2[c] * Wv[e])); }
        { const int j = e >> 8, c = e & 255;
          g_WoT[e] = __float2half(Wo[c * 256 + j]); }
        if (e < CCH * 128) {
            const int c = e >> 7, j = e & 127;
            g_W2w[e] = __uint_as_float(f2tf32(g1[c] * wpad_val(Ww, Wk, c, j)));
        }
    } else if (bx == 256) {
        float u = 0.f, v = 0.f;
        for (int c = 0; c < CCH; ++c) {
            const float w = Wv[c * 256 + t];
            u = fmaf(g2[c], w, u);
            v = fmaf(b2[c], w, v);
        }
        g_uv[t] = u; g_vv[t] = v + bv[t];
    } else {
        if (t < 128) {
            float u = 0.f, v = 0.f;
            for (int c = 0; c < CCH; ++c) {
                const float w = wpad_val(Ww, Wk, c, t);
                u = fmaf(g1[c], w, u);
                v = fmaf(b1[c], w, v);
            }
            const float bp = (t < 72) ? bw[t] : ((t < 81) ? bk[t - 72] : 0.f);
            g_uw[t] = u; g_vw[t] = v + bp;
        } else if (t < 128 + PPTS) {
            const int p = t - 128;
            float a = 0.f, bs = 0.f;
            for (int c = 0; c < CCH; ++c) {
                a  = fmaf(b1[c], Wk[c * PPTS + p], a);
                bs = fmaf(g1[c], Wk[c * PPTS + p], bs);
            }
            g_cA[p] = a + bk[p];
            g_cB[p] = bs;
        }
    }
}

// ---------------- K3: tf32 GEMM, cp.async pipeline, fused LN stats ----------
// MODE 0 (3-stage): g_value[m, j0+j] = rstd*(x2 @ W2v) - rstd*mean*u + v
// MODE 1 (2-stage): g_logits + fp32 keypoint offsets -> kp_out (stats+offs fused)
template <int MODE>
__global__ __launch_bounds__(256, 2) void gemm_tf32(const float* __restrict__ feats,
                                                    const float* __restrict__ Wk,
                                                    const float* __restrict__ gamma1,
                                                    const float* __restrict__ anchor,
                                                    float* __restrict__ kp_out) {
    extern __shared__ char smem_raw[];
    const int STG = 32 * PADM;                       // floats per stage matrix
    const int NSTG = (MODE == 0) ? 3 : 2;
    float* Asf = reinterpret_cast<float*>(smem_raw);
    float* Bsf = Asf + NSTG * STG;
    float* mean_s = Bsf + NSTG * STG;
    float* rstd_s = mean_s + 128;
    float* u_s = rstd_s + 128;
    float* v_s = u_s + 128;
    float* red1 = v_s + 128;    // 256
    float* red2 = red1 + 256;   // 256
    float* wk_s = red2 + 256;   // MODE1: 2304
    float* cA_s = wk_s + 2304;  // 16
    float* cB_s = cA_s + 16;    // 16

    const float* W2   = (MODE == 0) ? g_W2v : g_W2w;
    const float* uvec = (MODE == 0) ? g_uv : g_uw;
    const float* vvec = (MODE == 0) ? g_vv : g_vw;

    const int t = threadIdx.x, lane = t & 31, wid = t >> 5;
    const int lk = lane & 3, lr = lane >> 2;
    const int mb = (wid & 1) * 64, nb = (wid >> 1) * 32;

    const int m0 = blockIdx.x * 128, j0 = blockIdx.y * 128;
    const int b = m0 >> 15, n0 = m0 & (HW - 1);
    const int LDB = (MODE == 0) ? 256 : 128;

    if (t < 128) {
        u_s[t] = uvec[j0 + t];
        v_s[t] = vvec[j0 + t];
    }
    if (MODE == 1) {
        for (int idx = t; idx < CCH * PPTS; idx += 256) {
            const int c = idx / PPTS;
            wk_s[idx] = gamma1[c] * Wk[idx];
        }
        if (t < PPTS) { cA_s[t] = g_cA[t]; cB_s[t] = g_cB[t]; }
    }

    const float* fb = feats + ((size_t)b << 23) + n0;
    const uint32_t sbA = smem_u32(Asf);
    const uint32_t sbB = smem_u32(Bsf);
    const int fc0 = t >> 5;              // 0..7
    const int fm4 = (t & 31) << 2;       // 0..124

    auto fill = [&](int s, int kt) {
        const int k0 = kt * 32;
        const uint32_t aoff = sbA + (uint32_t)s * STG * 4;
        const uint32_t boff = sbB + (uint32_t)s * STG * 4;
#pragma unroll
        for (int i = 0; i < 4; ++i) {
            const int c = fc0 + i * 8;
            CP16(aoff + (uint32_t)(c * PADM + fm4) * 4,
                 fb + ((size_t)(k0 + c) << 15) + fm4);
            CP16(boff + (uint32_t)(c * PADM + fm4) * 4,
                 W2 + (size_t)(k0 + c) * LDB + j0 + fm4);
        }
    };

    float acc[4][4][4];
#pragma unroll
    for (int mi = 0; mi < 4; ++mi)
#pragma unroll
        for (int ni = 0; ni < 4; ++ni)
#pragma unroll
            for (int q = 0; q < 4; ++q) acc[mi][ni][q] = 0.f;

    // in-kernel LN stats (+offsets for MODE 1)
    float s1 = 0.f, s2acc = 0.f;
    float o[PPTS];
#pragma unroll
    for (int p = 0; p < PPTS; ++p) o[p] = 0.f;
    const int sm = t & 127, sh = (t >> 7) << 4;   // row, k-half offset

    auto do_mma = [&](const float* Ast, const float* Bst) {
        const uint32_t* As = reinterpret_cast<const uint32_t*>(Ast);
        const uint32_t* Bs = reinterpret_cast<const uint32_t*>(Bst);
#pragma unroll
        for (int ks = 0; ks < 4; ++ks) {
            const int kb = ks * 8;
            uint32_t a[4][4];
#pragma unroll
            for (int mi = 0; mi < 4; ++mi) {
                const uint32_t* Ab = &As[(kb + lk) * PADM + mb + 16 * mi + lr];
                a[mi][0] = Ab[0];
                a[mi][1] = Ab[8];
                a[mi][2] = Ab[4 * PADM];
                a[mi][3] = Ab[4 * PADM + 8];
            }
            uint32_t bf[4][2];
#pragma unroll
            for (int ni = 0; ni < 4; ++ni) {
                const uint32_t* Bb = &Bs[(kb + lk) * PADM + nb + 8 * ni + lr];
                bf[ni][0] = Bb[0];
                bf[ni][1] = Bb[4 * PADM];
            }
#pragma unroll
            for (int mi = 0; mi < 4; ++mi)
#pragma unroll
                for (int ni = 0; ni < 4; ++ni) {
                    asm volatile(
                        "mma.sync.aligned.m16n8k8.row.col.f32.tf32.tf32.f32 "
                        "{%0,%1,%2,%3}, {%4,%5,%6,%7}, {%8,%9}, {%0,%1,%2,%3};"
                        : "+f"(acc[mi][ni][0]), "+f"(acc[mi][ni][1]),
                          "+f"(acc[mi][ni][2]), "+f"(acc[mi][ni][3])
                        : "r"(a[mi][0]), "r"(a[mi][1]), "r"(a[mi][2]), "r"(a[mi][3]),
                          "r"(bf[ni][0]), "r"(bf[ni][1]));
                }
        }
    };

    if (MODE == 0) {
        fill(0, 0); CPCOMMIT();
        fill(1, 1); CPCOMMIT();
        for (int kt = 0; kt < 8; ++kt) {
            CPWAIT1();
            __syncthreads();
            if (kt + 2 < 8) fill((kt + 2) % 3, kt + 2);
            CPCOMMIT();
            const float* Ast = Asf + (kt % 3) * STG;
#pragma unroll
            for (int cc = 0; cc < 16; ++cc) {
                const float v = Ast[(sh + cc) * PADM + sm];
                s1 += v; s2acc = fmaf(v, v, s2acc);
            }
            do_mma(Ast, Bsf + (kt % 3) * STG);
        }
    } else {
        fill(0, 0); CPCOMMIT();
        for (int kt = 0; kt < 8; ++kt) {
            if (kt + 1 < 8) fill((kt + 1) & 1, kt + 1);
            CPCOMMIT();
            CPWAIT1();
            __syncthreads();
            const float* Ast = Asf + (kt & 1) * STG;
#pragma unroll
            for (int cc = 0; cc < 16; ++cc) {
                const float v = Ast[(sh + cc) * PADM + sm];
                s1 += v; s2acc = fmaf(v, v, s2acc);
                const float* wrow = wk_s + (kt * 32 + sh + cc) * PPTS;
#pragma unroll
                for (int p = 0; p < PPTS; ++p)
                    o[p] = fmaf(v, wrow[p], o[p]);
            }
            do_mma(Ast, Bsf + (kt & 1) * STG);
            __syncthreads();
        }
    }

    // ---- reduce LN stats ----
    red1[t] = s1; red2[t] = s2acc;
    __syncthreads();
    if (t < 128) {
        const float S1 = red1[t] + red1[t + 128];
        const float S2 = red2[t] + red2[t + 128];
        const float m = S1 * (1.f / 256.f);
        mean_s[t] = m;
        rstd_s[t] = rsqrtf(S2 * (1.f / 256.f) - m * m + 1e-5f);
    }
    __syncthreads();

    // ---- MODE 1: reduce offsets, emit keypoints ----
    if (MODE == 1) {
        float ax = 0.f, ay = 0.f;
        if (t < 128) {
            ax = anchor[2 * (m0 + t)];
            ay = anchor[2 * (m0 + t) + 1];
        }
#pragma unroll
        for (int p = 0; p < PPTS; ++p) {
            red1[t] = o[p];
            __syncthreads();
            if (t < 128) {
                const float S = red1[t] + red1[t + 128];
                const float off = rstd_s[t] * (S - mean_s[t] * cB_s[p]) + cA_s[p];
                kp_out[((size_t)(m0 + t) * PPTS + p) * 2]     = ax + off;
                kp_out[((size_t)(m0 + t) * PPTS + p) * 2 + 1] = ay;
            }
            __syncthreads();
        }
    }

    // ---- epilogue: C = rstd*D - rstd*mean*u + v ----
#pragma unroll
    for (int mi = 0; mi < 4; ++mi) {
        const int ml = mb + 16 * mi + lr;
        const float r0 = rstd_s[ml],     rm0 = r0 * mean_s[ml];
        const float r1 = rstd_s[ml + 8], rm1 = r1 * mean_s[ml + 8];
#pragma unroll
        for (int ni = 0; ni < 4; ++ni) {
            const int jc = nb + 8 * ni + 2 * lk;
            const float u0 = u_s[jc], u1 = u_s[jc + 1];
            const float v0 = v_s[jc], v1 = v_s[jc + 1];
            const float c00 = fmaf(r0, acc[mi][ni][0], fmaf(-rm0, u0, v0));
            const float c01 = fmaf(r0, acc[mi][ni][1], fmaf(-rm0, u1, v1));
            const float c10 = fmaf(r1, acc[mi][ni][2], fmaf(-rm1, u0, v0));
            const float c11 = fmaf(r1, acc[mi][ni][3], fmaf(-rm1, u1, v1));
            if (MODE == 0) {
                const __half2 h0 = __floats2half2_rn(c00, c01);
                const __half2 h1 = __floats2half2_rn(c10, c11);
                *reinterpret_cast<__half2*>(g_value + (size_t)(m0 + ml) * 256 + j0 + jc) = h0;
                *reinterpret_cast<__half2*>(g_value + (size_t)(m0 + ml + 8) * 256 + j0 + jc) = h1;
            } else if (jc < 72) {
                float2 r0v; r0v.x = c00; r0v.y = c01;
                float2 r1v; r1v.x = c10; r1v.y = c11;
                *reinterpret_cast<float2*>(g_logits + (size_t)(m0 + ml) * 128 + jc) = r0v;
                *reinterpret_cast<float2*>(g_logits + (size_t)(m0 + ml + 8) * 128 + jc) = r1v;
            }
        }
    }
}

// ---------------- K6: fp16 GEMM (out = Wo^T @ agg^T + bo), cp.async 3-stage -
__global__ __launch_bounds__(256, 2) void gemm_f16(const float* __restrict__ bias,
                                                   float* __restrict__ out) {
    extern __shared__ char smem_raw[];
    const int STGH = 128 * PADK;                        // halves per stage matrix
    __half* Ash = reinterpret_cast<__half*>(smem_raw);  // 3 stages (Wo^T tile)
    __half* Bsh = Ash + 3 * STGH;                       // 3 stages (agg tile)

    const int t = threadIdx.x, lane = t & 31, wid = t >> 5;
    const int lk = lane & 3, lr = lane >> 2;
    const int mb = (wid & 1) * 64, nb = (wid >> 1) * 32;

    const int n0 = blockIdx.x * 128, j0 = blockIdx.y * 128;
    const int b = n0 >> 15, nbase = n0 & (HW - 1);

    const uint32_t sbA = smem_u32(Ash);
    const uint32_t sbB = smem_u32(Bsh);

    auto fill = [&](int s, int kt) {
        const int k0 = kt * 32;
#pragma unroll
        for (int i = 0; i < 2; ++i) {
            const int idx = t + i * 256;
            const int row = idx >> 2, seg = (idx & 3) << 3;   // seg in halves
            CP16(sbA + (uint32_t)s * STGH * 2 + (uint32_t)(row * PADK + seg) * 2,
                 g_WoT + (size_t)(j0 + row) * 256 + k0 + seg);
            CP16(sbB + (uint32_t)s * STGH * 2 + (uint32_t)(row * PADK + seg) * 2,
                 g_agg + ((size_t)(n0 + row) << 8) + k0 + seg);
        }
    };

    float acc[4][4][4];
#pragma unroll
    for (int mi = 0; mi < 4; ++mi)
#pragma unroll
        for (int ni = 0; ni < 4; ++ni)
#pragma unroll
            for (int q = 0; q < 4; ++q) acc[mi][ni][q] = 0.f;

    fill(0, 0); CPCOMMIT();
    fill(1, 1); CPCOMMIT();

    for (int kt = 0; kt < 8; ++kt) {
        CPWAIT1();
        __syncthreads();
        if (kt + 2 < 8) fill((kt + 2) % 3, kt + 2);
        CPCOMMIT();

        const __half* At = Ash + (kt % 3) * STGH;
        const __half* Bt = Bsh + (kt % 3) * STGH;
#pragma unroll
        for (int ks = 0; ks < 2; ++ks) {
            const int kk = ks * 16 + lk * 2;
            uint32_t a[4][4];
#pragma unroll
            for (int mi = 0; mi < 4; ++mi) {
                const __half* Ab = At + (mb + 16 * mi + lr) * PADK + kk;
                a[mi][0] = *reinterpret_cast<const uint32_t*>(Ab);
                a[mi][1] = *reinterpret_cast<const uint32_t*>(Ab + 8 * PADK);
                a[mi][2] = *reinterpret_cast<const uint32_t*>(Ab + 8);
                a[mi][3] = *reinterpret_cast<const uint32_t*>(Ab + 8 * PADK + 8);
            }
            uint32_t bf[4][2];
#pragma unroll
            for (int ni = 0; ni < 4; ++ni) {
                const __half* Bb = Bt + (nb + 8 * ni + lr) * PADK + kk;
                bf[ni][0] = *reinterpret_cast<const uint32_t*>(Bb);
                bf[ni][1] = *reinterpret_cast<const uint32_t*>(Bb + 8);
            }
#pragma unroll
            for (int mi = 0; mi < 4; ++mi)
#pragma unroll
                for (int ni = 0; ni < 4; ++ni) {
                    asm volatile(
                        "mma.sync.aligned.m16n8k16.row.col.f32.f16.f16.f32 "
                        "{%0,%1,%2,%3}, {%4,%5,%6,%7}, {%8,%9}, {%0,%1,%2,%3};"
                        : "+f"(acc[mi][ni][0]), "+f"(acc[mi][ni][1]),
                          "+f"(acc[mi][ni][2]), "+f"(acc[mi][ni][3])
                        : "r"(a[mi][0]), "r"(a[mi][1]), "r"(a[mi][2]), "r"(a[mi][3]),
                          "r"(bf[ni][0]), "r"(bf[ni][1]));
                }
        }
    }

    // ---- epilogue: out[b][j][n] ----
#pragma unroll
    for (int mi = 0; mi < 4; ++mi) {
        const int j = j0 + mb + 16 * mi + lr;
        const float br0 = __ldg(bias + j);
        const float br1 = __ldg(bias + j + 8);
        float* d0 = out + (((size_t)(b * CCH + j)) << 15) + nbase;
        float* d1 = out + (((size_t)(b * CCH + j + 8)) << 15) + nbase;
#pragma unroll
        for (int ni = 0; ni < 4; ++ni) {
            const int cb = nb + 8 * ni + 2 * lk;
            float2 r0, r1;
            r0.x = acc[mi][ni][0] + br0;
            r0.y = acc[mi][ni][1] + br0;
            r1.x = acc[mi][ni][2] + br1;
            r1.y = acc[mi][ni][3] + br1;
            *reinterpret_cast<float2*>(d0 + cb) = r0;
            *reinterpret_cast<float2*>(d1 + cb) = r1;
        }
    }
}

// ---------------- K5: fused softmax + deformable gather (8 px/block) --------
__global__ __launch_bounds__(256) void agg_kernel(const float* __restrict__ kp) {
    __shared__ float w_s[8][72];
    __shared__ int   sxi[8][PPTS][2];
    __shared__ float sxy[8][PPTS][2];

    const int t = threadIdx.x;
    const int pg0 = blockIdx.x << 3;

    if (t < 64) {
        const int lp = t >> 3, g = t & 7;
        const float* row = g_logits + (size_t)(pg0 + lp) * 128 + g;
        float l[PPTS];
        float mx = -1e30f;
#pragma unroll
        for (int p = 0; p < PPTS; ++p) { l[p] = row[p * 8]; mx = fmaxf(mx, l[p]); }
        float s = 0.f;
#pragma unroll
        for (int p = 0; p < PPTS; ++p) { l[p] = __expf(l[p] - mx); s += l[p]; }
        const float inv = 1.f / s;
#pragma unroll
        for (int p = 0; p < PPTS; ++p) w_s[lp][p * 8 + g] = l[p] * inv;
    }
    if (t >= 128 && t < 128 + 8 * PPTS) {
        const int idx = t - 128;
        const int lp = idx / PPTS, p = idx - lp * PPTS;
        const size_t kidx = ((size_t)(pg0 + lp) * PPTS + p) * 2;
        const float x = kp[kidx] * (float)WWD - 0.5f;
        const float y = kp[kidx + 1] * (float)HH - 0.5f;
        const float xf = floorf(x), yf = floorf(y);
        sxi[lp][p][0] = (int)xf; sxi[lp][p][1] = (int)yf;
        sxy[lp][p][0] = x - xf;  sxy[lp][p][1] = y - yf;
    }
    __syncthreads();

    const int lp = t >> 5, lane = t & 31;
    const int c = lane << 3;          // 8 channels / thread
    const int g = lane >> 2;
    const int pg = pg0 + lp, b = pg >> 15;
    const __half* vb = g_value + ((size_t)b << 23) + c;

    float acc[8];
#pragma unroll
    for (int q = 0; q < 8; ++q) acc[q] = 0.f;

#pragma unroll
    for (int p = 0; p < PPTS; ++p) {
        const int x0 = sxi[lp][p][0], y0 = sxi[lp][p][1];
        const float wx = sxy[lp][p][0], wy = sxy[lp][p][1];
        const float wp = w_s[lp][p * 8 + g];
        const bool yv0 = (y0 >= 0) & (y0 < HH);
        const bool yv1 = (y0 + 1 >= 0) & (y0 + 1 < HH);
        const bool xv0 = (x0 >= 0) & (x0 < WWD);
        const bool xv1 = (x0 + 1 >= 0) & (x0 + 1 < WWD);
        uint4 r00 = {0,0,0,0}, r01 = {0,0,0,0}, r10 = {0,0,0,0}, r11 = {0,0,0,0};
        if (yv0 && xv0) r00 = *reinterpret_cast<const uint4*>(vb + ((size_t)(y0 * WWD + x0) << 8));
        if (yv0 && xv1) r01 = *reinterpret_cast<const uint4*>(vb + ((size_t)(y0 * WWD + x0 + 1) << 8));
        if (yv1 && xv0) r10 = *reinterpret_cast<const uint4*>(vb + ((size_t)((y0 + 1) * WWD + x0) << 8));
        if (yv1 && xv1) r11 = *reinterpret_cast<const uint4*>(vb + ((size_t)((y0 + 1) * WWD + x0 + 1) << 8));
        const float ww00 = wp * (1.f - wx) * (1.f - wy);
        const float ww01 = wp * wx * (1.f - wy);
        const float ww10 = wp * (1.f - wx) * wy;
        const float ww11 = wp * wx * wy;
        const uint32_t* q00 = reinterpret_cast<const uint32_t*>(&r00);
        const uint32_t* q01 = reinterpret_cast<const uint32_t*>(&r01);
        const uint32_t* q10 = reinterpret_cast<const uint32_t*>(&r10);
        const uint32_t* q11 = reinterpret_cast<const uint32_t*>(&r11);
#pragma unroll
        for (int q = 0; q < 4; ++q) {
            const float2 f00 = h2f(q00[q]), f01 = h2f(q01[q]);
            const float2 f10 = h2f(q10[q]), f11 = h2f(q11[q]);
            acc[2*q]   = fmaf(ww00, f00.x, fmaf(ww01, f01.x,
                          fmaf(ww10, f10.x, fmaf(ww11, f11.x, acc[2*q]))));
            acc[2*q+1] = fmaf(ww00, f00.y, fmaf(ww01, f01.y,
                          fmaf(ww10, f10.y, fmaf(ww11, f11.y, acc[2*q+1]))));
        }
    }
    uint4 st;
    uint32_t* sp = reinterpret_cast<uint32_t*>(&st);
#pragma unroll
    for (int q = 0; q < 4; ++q) {
        const __half2 h = __floats2half2_rn(acc[2*q], acc[2*q+1]);
        sp[q] = *reinterpret_cast<const uint32_t*>(&h);
    }
    *reinterpret_cast<uint4*>(g_agg + ((size_t)pg << 8) + c) = st;
}

// ---------------- launch -----------------------------------------------------
#define SMEM_T0 ((6 * 32 * PADM + 1024) * 4)              // 108544 B
#define SMEM_T1 ((4 * 32 * PADM + 1024 + 2304 + 32) * 4)  // 83072 B
#define SMEM_H  (6 * 128 * PADK * 2)                      // 61440 B

extern "C" void kernel_launch(void* const* d_in, const int* in_sizes, int n_in,
                              void* d_out, int out_size) {
    const float* feats1 = (const float*)d_in[0];
    const float* feats2 = (const float*)d_in[1];
    const float* anchor = (const float*)d_in[2];
    const float* n1g = (const float*)d_in[3];
    const float* n1b = (const float*)d_in[4];
    const float* n2g = (const float*)d_in[5];
    const float* n2b = (const float*)d_in[6];
    const float* Wv  = (const float*)d_in[7];
    const float* bv  = (const float*)d_in[8];
    const float* Ww  = (const float*)d_in[9];
    const float* bw  = (const float*)d_in[10];
    const float* Wk  = (const float*)d_in[11];
    const float* bk  = (const float*)d_in[12];
    const float* Wo  = (const float*)d_in[13];
    const float* bo  = (const float*)d_in[14];

    float* out    = (float*)d_out;
    float* kp_out = out + (size_t)16777216;   // B*C*H*W

    cudaFuncSetAttribute(gemm_tf32<0>, cudaFuncAttributeMaxDynamicSharedMemorySize, SMEM_T0);
    cudaFuncSetAttribute(gemm_tf32<1>, cudaFuncAttributeMaxDynamicSharedMemorySize, SMEM_T1);
    cudaFuncSetAttribute(gemm_f16, cudaFuncAttributeMaxDynamicSharedMemorySize, SMEM_H);

    prep_all<<<258, 256>>>(Wv, n2g, n2b, bv, Wo, n1g, n1b, Ww, bw, Wk, bk);
    gemm_tf32<0><<<dim3(512, 2), 256, SMEM_T0>>>(feats2, nullptr, nullptr, nullptr, nullptr);
    gemm_tf32<1><<<dim3(512, 1), 256, SMEM_T1>>>(feats1, Wk, n1g, anchor, kp_out);
    agg_kernel<<<NPIX / 8, 256>>>(kp_out);
    gemm_f16<<<dim3(512, 2), 256, SMEM_H>>>(bo, out);
}

// round 11
// speedup vs baseline: 3.3166x; 1.0334x over previous
#include <cuda_runtime.h>
#include <cuda_fp16.h>
#include <cstdint>
#include <math.h>

// Problem dims
#define HW   32768
#define CCH  256
#define HH   128
#define WWD  256
#define NPIX 65536      // B * HW
#define PPTS 9
#define GRP  8

#define PADM 136        // tf32 SMEM row stride (floats)
#define PADK 40         // f16 SMEM row stride (halves)

// ---------------- scratch (static device globals; no allocation) ------------
__device__ __half g_value[(size_t)NPIX * CCH];    // (pixel, j) fp16
__device__ float  g_logits[(size_t)NPIX * 128];   // cols 0..71 consumed
__device__ __half g_agg[(size_t)NPIX * CCH];      // fp16
__device__ float  g_W2v[CCH * 256];               // tf32(gamma2*Wv) [c][j]
__device__ float  g_W2w[CCH * 128];               // tf32(gamma1*[Ww|Wk|0]) [c][j]
__device__ __half g_WoT[256 * 256];               // Wo^T fp16 [j][c]
__device__ float  g_uv[256], g_vv[256];           // mode0 epilogue vectors
__device__ float  g_uw[128], g_vw[128];           // mode1 epilogue vectors
__device__ float  g_cA[16], g_cB[16];             // offset epilogue constants

__device__ __forceinline__ uint32_t f2tf32(float f) {
    uint32_t r;
    asm("cvt.rna.tf32.f32 %0, %1;" : "=r"(r) : "f"(f));
    return r;
}
__device__ __forceinline__ uint32_t smem_u32(const void* p) {
    uint32_t a;
    asm("{ .reg .u64 t; cvta.to.shared.u64 t, %1; cvt.u32.u64 %0, t; }" : "=r"(a) : "l"(p));
    return a;
}
#define CP16(dst, src) \
    asm volatile("cp.async.cg.shared.global [%0], [%1], 16;" :: "r"(dst), "l"(src))
#define CPCOMMIT() asm volatile("cp.async.commit_group;" ::)
#define CPWAIT1()  asm volatile("cp.async.wait_group 1;" ::)

__device__ __forceinline__ float wpad_val(const float* __restrict__ Ww,
                                          const float* __restrict__ Wk,
                                          int c, int j) {
    if (j < 72) return Ww[c * 72 + j];
    if (j < 81) return Wk[c * 9 + (j - 72)];
    return 0.f;
}

// ---------------- K2: single fused prep (weight images + epilogue vectors) --
__global__ __launch_bounds__(256) void prep_all(const float* __restrict__ Wv,
                                                const float* __restrict__ g2,
                                                const float* __restrict__ b2,
                                                const float* __restrict__ bv,
                                                const float* __restrict__ Wo,
                                                const float* __restrict__ g1,
                                                const float* __restrict__ b1,
                                                const float* __restrict__ Ww,
                                                const float* __restrict__ bw,
                                                const float* __restrict__ Wk,
                                                const float* __restrict__ bk) {
    const int bx = blockIdx.x, t = threadIdx.x;
    if (bx < 256) {
        const int e = bx * 256 + t;
        { const int c = e >> 8;
          g_W2v[e] = __uint_as_float(f2tf32(g2[c] * Wv[e])); }
        { const int j = e >> 8, c = e & 255;
          g_WoT[e] = __float2half(Wo[c * 256 + j]); }
        if (e < CCH * 128) {
            const int c = e >> 7, j = e & 127;
            g_W2w[e] = __uint_as_float(f2tf32(g1[c] * wpad_val(Ww, Wk, c, j)));
        }
    } else if (bx == 256) {
        float u = 0.f, v = 0.f;
        for (int c = 0; c < CCH; ++c) {
            const float w = Wv[c * 256 + t];
            u = fmaf(g2[c], w, u);
            v = fmaf(b2[c], w, v);
        }
        g_uv[t] = u; g_vv[t] = v + bv[t];
    } else {
        if (t < 128) {
            float u = 0.f, v = 0.f;
            for (int c = 0; c < CCH; ++c) {
                const float w = wpad_val(Ww, Wk, c, t);
                u = fmaf(g1[c], w, u);
                v = fmaf(b1[c], w, v);
            }
            const float bp = (t < 72) ? bw[t] : ((t < 81) ? bk[t - 72] : 0.f);
            g_uw[t] = u; g_vw[t] = v + bp;
        } else if (t < 128 + PPTS) {
            const int p = t - 128;
            float a = 0.f, bs = 0.f;
            for (int c = 0; c < CCH; ++c) {
                a  = fmaf(b1[c], Wk[c * PPTS + p], a);
                bs = fmaf(g1[c], Wk[c * PPTS + p], bs);
            }
            g_cA[p] = a + bk[p];
            g_cB[p] = bs;
        }
    }
}

// ---------------- K3: tf32 GEMM, cp.async pipeline, fused LN stats ----------
// MODE 0 (3-stage): g_value[m, j0+j] = rstd*(x2 @ W2v) - rstd*mean*u + v
// MODE 1 (2-stage): g_logits + fp32 keypoint offsets -> kp_out (stats+offs fused)
template <int MODE>
__global__ __launch_bounds__(256, 2) void gemm_tf32(const float* __restrict__ feats,
                                                    const float* __restrict__ Wk,
                                                    const float* __restrict__ gamma1,
                                                    const float* __restrict__ anchor,
                                                    float* __restrict__ kp_out) {
    extern __shared__ char smem_raw[];
    const int STG = 32 * PADM;                       // floats per stage matrix
    const int NSTG = (MODE == 0) ? 3 : 2;
    float* Asf = reinterpret_cast<float*>(smem_raw);
    float* Bsf = Asf + NSTG * STG;
    float* mean_s = Bsf + NSTG * STG;
    float* rstd_s = mean_s + 128;
    float* u_s = rstd_s + 128;
    float* v_s = u_s + 128;
    float* red1 = v_s + 128;    // 256
    float* red2 = red1 + 256;   // 256
    float* wk_s = red2 + 256;   // MODE1: 2304
    float* cA_s = wk_s + 2304;  // 16
    float* cB_s = cA_s + 16;    // 16

    const float* W2   = (MODE == 0) ? g_W2v : g_W2w;
    const float* uvec = (MODE == 0) ? g_uv : g_uw;
    const float* vvec = (MODE == 0) ? g_vv : g_vw;

    const int t = threadIdx.x, lane = t & 31, wid = t >> 5;
    const int lk = lane & 3, lr = lane >> 2;
    const int mb = (wid & 1) * 64, nb = (wid >> 1) * 32;

    const int m0 = blockIdx.x * 128, j0 = blockIdx.y * 128;
    const int b = m0 >> 15, n0 = m0 & (HW - 1);
    const int LDB = (MODE == 0) ? 256 : 128;

    if (t < 128) {
        u_s[t] = uvec[j0 + t];
        v_s[t] = vvec[j0 + t];
    }
    if (MODE == 1) {
        for (int idx = t; idx < CCH * PPTS; idx += 256) {
            const int c = idx / PPTS;
            wk_s[idx] = gamma1[c] * Wk[idx];
        }
        if (t < PPTS) { cA_s[t] = g_cA[t]; cB_s[t] = g_cB[t]; }
    }

    const float* fb = feats + ((size_t)b << 23) + n0;
    const uint32_t sbA = smem_u32(Asf);
    const uint32_t sbB = smem_u32(Bsf);
    const int fc0 = t >> 5;              // 0..7
    const int fm4 = (t & 31) << 2;       // 0..124

    auto fill = [&](int s, int kt) {
        const int k0 = kt * 32;
        const uint32_t aoff = sbA + (uint32_t)s * STG * 4;
        const uint32_t boff = sbB + (uint32_t)s * STG * 4;
#pragma unroll
        for (int i = 0; i < 4; ++i) {
            const int c = fc0 + i * 8;
            CP16(aoff + (uint32_t)(c * PADM + fm4) * 4,
                 fb + ((size_t)(k0 + c) << 15) + fm4);
            CP16(boff + (uint32_t)(c * PADM + fm4) * 4,
                 W2 + (size_t)(k0 + c) * LDB + j0 + fm4);
        }
    };

    float acc[4][4][4];
#pragma unroll
    for (int mi = 0; mi < 4; ++mi)
#pragma unroll
        for (int ni = 0; ni < 4; ++ni)
#pragma unroll
            for (int q = 0; q < 4; ++q) acc[mi][ni][q] = 0.f;

    // in-kernel LN stats (+offsets for MODE 1)
    float s1 = 0.f, s2acc = 0.f;
    float o[PPTS];
#pragma unroll
    for (int p = 0; p < PPTS; ++p) o[p] = 0.f;
    const int sm = t & 127, sh = (t >> 7) << 4;   // row, k-half offset

    auto do_mma = [&](const float* Ast, const float* Bst) {
        const uint32_t* As = reinterpret_cast<const uint32_t*>(Ast);
        const uint32_t* Bs = reinterpret_cast<const uint32_t*>(Bst);
#pragma unroll
        for (int ks = 0; ks < 4; ++ks) {
            const int kb = ks * 8;
            uint32_t a[4][4];
#pragma unroll
            for (int mi = 0; mi < 4; ++mi) {
                const uint32_t* Ab = &As[(kb + lk) * PADM + mb + 16 * mi + lr];
                a[mi][0] = Ab[0];
                a[mi][1] = Ab[8];
                a[mi][2] = Ab[4 * PADM];
                a[mi][3] = Ab[4 * PADM + 8];
            }
            uint32_t bf[4][2];
#pragma unroll
            for (int ni = 0; ni < 4; ++ni) {
                const uint32_t* Bb = &Bs[(kb + lk) * PADM + nb + 8 * ni + lr];
                bf[ni][0] = Bb[0];
                bf[ni][1] = Bb[4 * PADM];
            }
#pragma unroll
            for (int mi = 0; mi < 4; ++mi)
#pragma unroll
                for (int ni = 0; ni < 4; ++ni) {
                    asm volatile(
                        "mma.sync.aligned.m16n8k8.row.col.f32.tf32.tf32.f32 "
                        "{%0,%1,%2,%3}, {%4,%5,%6,%7}, {%8,%9}, {%0,%1,%2,%3};"
                        : "+f"(acc[mi][ni][0]), "+f"(acc[mi][ni][1]),
                          "+f"(acc[mi][ni][2]), "+f"(acc[mi][ni][3])
                        : "r"(a[mi][0]), "r"(a[mi][1]), "r"(a[mi][2]), "r"(a[mi][3]),
                          "r"(bf[ni][0]), "r"(bf[ni][1]));
                }
        }
    };

    if (MODE == 0) {
        fill(0, 0); CPCOMMIT();
        fill(1, 1); CPCOMMIT();
        for (int kt = 0; kt < 8; ++kt) {
            CPWAIT1();
            __syncthreads();
            if (kt + 2 < 8) fill((kt + 2) % 3, kt + 2);
            CPCOMMIT();
            const float* Ast = Asf + (kt % 3) * STG;
#pragma unroll
            for (int cc = 0; cc < 16; ++cc) {
                const float v = Ast[(sh + cc) * PADM + sm];
                s1 += v; s2acc = fmaf(v, v, s2acc);
            }
            do_mma(Ast, Bsf + (kt % 3) * STG);
        }
    } else {
        fill(0, 0); CPCOMMIT();
        for (int kt = 0; kt < 8; ++kt) {
            if (kt + 1 < 8) fill((kt + 1) & 1, kt + 1);
            CPCOMMIT();
            CPWAIT1();
            __syncthreads();
            const float* Ast = Asf + (kt & 1) * STG;
#pragma unroll
            for (int cc = 0; cc < 16; ++cc) {
                const float v = Ast[(sh + cc) * PADM + sm];
                s1 += v; s2acc = fmaf(v, v, s2acc);
                const float* wrow = wk_s + (kt * 32 + sh + cc) * PPTS;
#pragma unroll
                for (int p = 0; p < PPTS; ++p)
                    o[p] = fmaf(v, wrow[p], o[p]);
            }
            do_mma(Ast, Bsf + (kt & 1) * STG);
            __syncthreads();
        }
    }

    // ---- reduce LN stats ----
    red1[t] = s1; red2[t] = s2acc;
    __syncthreads();
    if (t < 128) {
        const float S1 = red1[t] + red1[t + 128];
        const float S2 = red2[t] + red2[t + 128];
        const float m = S1 * (1.f / 256.f);
        mean_s[t] = m;
        rstd_s[t] = rsqrtf(S2 * (1.f / 256.f) - m * m + 1e-5f);
    }
    __syncthreads();

    // ---- MODE 1: reduce offsets, emit keypoints ----
    if (MODE == 1) {
        float ax = 0.f, ay = 0.f;
        if (t < 128) {
            ax = anchor[2 * (m0 + t)];
            ay = anchor[2 * (m0 + t) + 1];
        }
#pragma unroll
        for (int p = 0; p < PPTS; ++p) {
            red1[t] = o[p];
            __syncthreads();
            if (t < 128) {
                const float S = red1[t] + red1[t + 128];
                const float off = rstd_s[t] * (S - mean_s[t] * cB_s[p]) + cA_s[p];
                kp_out[((size_t)(m0 + t) * PPTS + p) * 2]     = ax + off;
                kp_out[((size_t)(m0 + t) * PPTS + p) * 2 + 1] = ay;
            }
            __syncthreads();
        }
    }

    // ---- epilogue: C = rstd*D - rstd*mean*u + v ----
#pragma unroll
    for (int mi = 0; mi < 4; ++mi) {
        const int ml = mb + 16 * mi + lr;
        const float r0 = rstd_s[ml],     rm0 = r0 * mean_s[ml];
        const float r1 = rstd_s[ml + 8], rm1 = r1 * mean_s[ml + 8];
#pragma unroll
        for (int ni = 0; ni < 4; ++ni) {
            const int jc = nb + 8 * ni + 2 * lk;
            const float u0 = u_s[jc], u1 = u_s[jc + 1];
            const float v0 = v_s[jc], v1 = v_s[jc + 1];
            const float c00 = fmaf(r0, acc[mi][ni][0], fmaf(-rm0, u0, v0));
            const float c01 = fmaf(r0, acc[mi][ni][1], fmaf(-rm0, u1, v1));
            const float c10 = fmaf(r1, acc[mi][ni][2], fmaf(-rm1, u0, v0));
            const float c11 = fmaf(r1, acc[mi][ni][3], fmaf(-rm1, u1, v1));
            if (MODE == 0) {
                const __half2 h0 = __floats2half2_rn(c00, c01);
                const __half2 h1 = __floats2half2_rn(c10, c11);
                *reinterpret_cast<__half2*>(g_value + (size_t)(m0 + ml) * 256 + j0 + jc) = h0;
                *reinterpret_cast<__half2*>(g_value + (size_t)(m0 + ml + 8) * 256 + j0 + jc) = h1;
            } else if (jc < 72) {
                float2 r0v; r0v.x = c00; r0v.y = c01;
                float2 r1v; r1v.x = c10; r1v.y = c11;
                *reinterpret_cast<float2*>(g_logits + (size_t)(m0 + ml) * 128 + jc) = r0v;
                *reinterpret_cast<float2*>(g_logits + (size_t)(m0 + ml + 8) * 128 + jc) = r1v;
            }
        }
    }
}

// ---------------- K6: fp16 GEMM (out = Wo^T @ agg^T + bo), cp.async 3-stage -
__global__ __launch_bounds__(256, 2) void gemm_f16(const float* __restrict__ bias,
                                                   float* __restrict__ out) {
    extern __shared__ char smem_raw[];
    const int STGH = 128 * PADK;                        // halves per stage matrix
    __half* Ash = reinterpret_cast<__half*>(smem_raw);  // 3 stages (Wo^T tile)
    __half* Bsh = Ash + 3 * STGH;                       // 3 stages (agg tile)

    const int t = threadIdx.x, lane = t & 31, wid = t >> 5;
    const int lk = lane & 3, lr = lane >> 2;
    const int mb = (wid & 1) * 64, nb = (wid >> 1) * 32;

    const int n0 = blockIdx.x * 128, j0 = blockIdx.y * 128;
    const int b = n0 >> 15, nbase = n0 & (HW - 1);

    const uint32_t sbA = smem_u32(Ash);
    const uint32_t sbB = smem_u32(Bsh);

    auto fill = [&](int s, int kt) {
        const int k0 = kt * 32;
#pragma unroll
        for (int i = 0; i < 2; ++i) {
            const int idx = t + i * 256;
            const int row = idx >> 2, seg = (idx & 3) << 3;   // seg in halves
            CP16(sbA + (uint32_t)s * STGH * 2 + (uint32_t)(row * PADK + seg) * 2,
                 g_WoT + (size_t)(j0 + row) * 256 + k0 + seg);
            CP16(sbB + (uint32_t)s * STGH * 2 + (uint32_t)(row * PADK + seg) * 2,
                 g_agg + ((size_t)(n0 + row) << 8) + k0 + seg);
        }
    };

    float acc[4][4][4];
#pragma unroll
    for (int mi = 0; mi < 4; ++mi)
#pragma unroll
        for (int ni = 0; ni < 4; ++ni)
#pragma unroll
            for (int q = 0; q < 4; ++q) acc[mi][ni][q] = 0.f;

    fill(0, 0); CPCOMMIT();
    fill(1, 1); CPCOMMIT();

    for (int kt = 0; kt < 8; ++kt) {
        CPWAIT1();
        __syncthreads();
        if (kt + 2 < 8) fill((kt + 2) % 3, kt + 2);
        CPCOMMIT();

        const __half* At = Ash + (kt % 3) * STGH;
        const __half* Bt = Bsh + (kt % 3) * STGH;
#pragma unroll
        for (int ks = 0; ks < 2; ++ks) {
            const int kk = ks * 16 + lk * 2;
            uint32_t a[4][4];
#pragma unroll
            for (int mi = 0; mi < 4; ++mi) {
                const __half* Ab = At + (mb + 16 * mi + lr) * PADK + kk;
                a[mi][0] = *reinterpret_cast<const uint32_t*>(Ab);
                a[mi][1] = *reinterpret_cast<const uint32_t*>(Ab + 8 * PADK);
                a[mi][2] = *reinterpret_cast<const uint32_t*>(Ab + 8);
                a[mi][3] = *reinterpret_cast<const uint32_t*>(Ab + 8 * PADK + 8);
            }
            uint32_t bf[4][2];
#pragma unroll
            for (int ni = 0; ni < 4; ++ni) {
                const __half* Bb = Bt + (nb + 8 * ni + lr) * PADK + kk;
                bf[ni][0] = *reinterpret_cast<const uint32_t*>(Bb);
                bf[ni][1] = *reinterpret_cast<const uint32_t*>(Bb + 8);
            }
#pragma unroll
            for (int mi = 0; mi < 4; ++mi)
#pragma unroll
                for (int ni = 0; ni < 4; ++ni) {
                    asm volatile(
                        "mma.sync.aligned.m16n8k16.row.col.f32.f16.f16.f32 "
                        "{%0,%1,%2,%3}, {%4,%5,%6,%7}, {%8,%9}, {%0,%1,%2,%3};"
                        : "+f"(acc[mi][ni][0]), "+f"(acc[mi][ni][1]),
                          "+f"(acc[mi][ni][2]), "+f"(acc[mi][ni][3])
                        : "r"(a[mi][0]), "r"(a[mi][1]), "r"(a[mi][2]), "r"(a[mi][3]),
                          "r"(bf[ni][0]), "r"(bf[ni][1]));
                }
        }
    }

    // ---- epilogue: out[b][j][n] ----
#pragma unroll
    for (int mi = 0; mi < 4; ++mi) {
        const int j = j0 + mb + 16 * mi + lr;
        const float br0 = __ldg(bias + j);
        const float br1 = __ldg(bias + j + 8);
        float* d0 = out + (((size_t)(b * CCH + j)) << 15) + nbase;
        float* d1 = out + (((size_t)(b * CCH + j + 8)) << 15) + nbase;
#pragma unroll
        for (int ni = 0; ni < 4; ++ni) {
            const int cb = nb + 8 * ni + 2 * lk;
            float2 r0, r1;
            r0.x = acc[mi][ni][0] + br0;
            r0.y = acc[mi][ni][1] + br0;
            r1.x = acc[mi][ni][2] + br1;
            r1.y = acc[mi][ni][3] + br1;
            *reinterpret_cast<float2*>(d0 + cb) = r0;
            *reinterpret_cast<float2*>(d1 + cb) = r1;
        }
    }
}

// ---------------- K5: fused softmax + gather, precomputed taps + fp16 blend -
__global__ __launch_bounds__(256) void agg_kernel(const float* __restrict__ kp) {
    __shared__ float  w_s[8][72];
    __shared__ int4   soff[8][PPTS];     // byte offsets of the 4 taps (0 if OOB)
    __shared__ float4 swgt[8][PPTS];     // tap weights (0 if OOB)

    const int t = threadIdx.x;
    const int pg0 = blockIdx.x << 3;

    if (t < 64) {
        const int lp = t >> 3, g = t & 7;
        const float* row = g_logits + (size_t)(pg0 + lp) * 128 + g;
        float l[PPTS];
        float mx = -1e30f;
#pragma unroll
        for (int p = 0; p < PPTS; ++p) { l[p] = row[p * 8]; mx = fmaxf(mx, l[p]); }
        float s = 0.f;
#pragma unroll
        for (int p = 0; p < PPTS; ++p) { l[p] = __expf(l[p] - mx); s += l[p]; }
        const float inv = 1.f / s;
#pragma unroll
        for (int p = 0; p < PPTS; ++p) w_s[lp][p * 8 + g] = l[p] * inv;
    }
    if (t >= 128 && t < 128 + 8 * PPTS) {
        const int idx = t - 128;
        const int lp = idx / PPTS, p = idx - lp * PPTS;
        const size_t kidx = ((size_t)(pg0 + lp) * PPTS + p) * 2;
        const float x = kp[kidx] * (float)WWD - 0.5f;
        const float y = kp[kidx + 1] * (float)HH - 0.5f;
        const float xf = floorf(x), yf = floorf(y);
        const int x0 = (int)xf, y0 = (int)yf;
        const float wx = x - xf, wy = y - yf;
        const bool xv0 = (x0 >= 0) & (x0 < WWD);
        const bool xv1 = (x0 + 1 >= 0) & (x0 + 1 < WWD);
        const bool yv0 = (y0 >= 0) & (y0 < HH);
        const bool yv1 = (y0 + 1 >= 0) & (y0 + 1 < HH);
        int4 off;
        off.x = (yv0 && xv0) ? ((y0 * WWD + x0) << 9) : 0;
        off.y = (yv0 && xv1) ? ((y0 * WWD + x0 + 1) << 9) : 0;
        off.z = (yv1 && xv0) ? (((y0 + 1) * WWD + x0) << 9) : 0;
        off.w = (yv1 && xv1) ? (((y0 + 1) * WWD + x0 + 1) << 9) : 0;
        float4 wt;
        wt.x = (yv0 && xv0) ? (1.f - wx) * (1.f - wy) : 0.f;
        wt.y = (yv0 && xv1) ? wx * (1.f - wy) : 0.f;
        wt.z = (yv1 && xv0) ? (1.f - wx) * wy : 0.f;
        wt.w = (yv1 && xv1) ? wx * wy : 0.f;
        soff[lp][p] = off;
        swgt[lp][p] = wt;
    }
    __syncthreads();

    const int lp = t >> 5, lane = t & 31;
    const int c = lane << 3;          // 8 channels / thread
    const int g = lane >> 2;
    const int pg = pg0 + lp, b = pg >> 15;
    const char* vbb = reinterpret_cast<const char*>(g_value + ((size_t)b << 23) + c);

    float fa[8];
#pragma unroll
    for (int q = 0; q < 8; ++q) fa[q] = 0.f;

#pragma unroll
    for (int p = 0; p < PPTS; ++p) {
        const int4 off = soff[lp][p];
        const float4 wt = swgt[lp][p];
        const float wp = w_s[lp][p * 8 + g];
        const __half2 hw00 = __float2half2_rn(wp * wt.x);
        const __half2 hw01 = __float2half2_rn(wp * wt.y);
        const __half2 hw10 = __float2half2_rn(wp * wt.z);
        const __half2 hw11 = __float2half2_rn(wp * wt.w);
        const uint4 r00 = *reinterpret_cast<const uint4*>(vbb + off.x);
        const uint4 r01 = *reinterpret_cast<const uint4*>(vbb + off.y);
        const uint4 r10 = *reinterpret_cast<const uint4*>(vbb + off.z);
        const uint4 r11 = *reinterpret_cast<const uint4*>(vbb + off.w);
        const __half2* h00 = reinterpret_cast<const __half2*>(&r00);
        const __half2* h01 = reinterpret_cast<const __half2*>(&r01);
        const __half2* h10 = reinterpret_cast<const __half2*>(&r10);
        const __half2* h11 = reinterpret_cast<const __half2*>(&r11);
#pragma unroll
        for (int q = 0; q < 4; ++q) {
            __half2 bl = __hmul2(hw00, h00[q]);
            bl = __hfma2(hw01, h01[q], bl);
            bl = __hfma2(hw10, h10[q], bl);
            bl = __hfma2(hw11, h11[q], bl);
            const float2 f = __half22float2(bl);
            fa[2 * q]     += f.x;
            fa[2 * q + 1] += f.y;
        }
    }
    uint4 st;
    uint32_t* sp = reinterpret_cast<uint32_t*>(&st);
#pragma unroll
    for (int q = 0; q < 4; ++q) {
        const __half2 h = __floats2half2_rn(fa[2 * q], fa[2 * q + 1]);
        sp[q] = *reinterpret_cast<const uint32_t*>(&h);
    }
    *reinterpret_cast<uint4*>(g_agg + ((size_t)pg << 8) + c) = st;
}

// ---------------- launch -----------------------------------------------------
#define SMEM_T0 ((6 * 32 * PADM + 1024) * 4)              // 108544 B
#define SMEM_T1 ((4 * 32 * PADM + 1024 + 2304 + 32) * 4)  // 83072 B
#define SMEM_H  (6 * 128 * PADK * 2)                      // 61440 B

extern "C" void kernel_launch(void* const* d_in, const int* in_sizes, int n_in,
                              void* d_out, int out_size) {
    const float* feats1 = (const float*)d_in[0];
    const float* feats2 = (const float*)d_in[1];
    const float* anchor = (const float*)d_in[2];
    const float* n1g = (const float*)d_in[3];
    const float* n1b = (const float*)d_in[4];
    const float* n2g = (const float*)d_in[5];
    const float* n2b = (const float*)d_in[6];
    const float* Wv  = (const float*)d_in[7];
    const float* bv  = (const float*)d_in[8];
    const float* Ww  = (const float*)d_in[9];
    const float* bw  = (const float*)d_in[10];
    const float* Wk  = (const float*)d_in[11];
    const float* bk  = (const float*)d_in[12];
    const float* Wo  = (const float*)d_in[13];
    const float* bo  = (const float*)d_in[14];

    float* out    = (float*)d_out;
    float* kp_out = out + (size_t)16777216;   // B*C*H*W

    cudaFuncSetAttribute(gemm_tf32<0>, cudaFuncAttributeMaxDynamicSharedMemorySize, SMEM_T0);
    cudaFuncSetAttribute(gemm_tf32<1>, cudaFuncAttributeMaxDynamicSharedMemorySize, SMEM_T1);
    cudaFuncSetAttribute(gemm_f16, cudaFuncAttributeMaxDynamicSharedMemorySize, SMEM_H);

    prep_all<<<258, 256>>>(Wv, n2g, n2b, bv, Wo, n1g, n1b, Ww, bw, Wk, bk);
    gemm_tf32<0><<<dim3(512, 2), 256, SMEM_T0>>>(feats2, nullptr, nullptr, nullptr, nullptr);
    gemm_tf32<1><<<dim3(512, 1), 256, SMEM_T1>>>(feats1, Wk, n1g, anchor, kp_out);
    agg_kernel<<<NPIX / 8, 256>>>(kp_out);
    gemm_f16<<<dim3(512, 2), 256, SMEM_H>>>(bo, out);
}